// round 5
// baseline (speedup 1.0000x reference)
#include <cuda_runtime.h>
#include <cstdint>
#include <cstddef>

#define NN 50000
#define NE 800000
#define INDIM 256
#define HID 256
#define OUTD 64
#define NH 4

// ---------------- device scratch (static allocation only) ----------------
__device__ int   g_deg[NN];
__device__ int   g_cursor[NN];
__device__ int   g_rowptr[NN + 1];
__device__ int   g_edst[NE];
__device__ float g_eelem[NE];
__device__ __align__(16) float g_hidden[(size_t)NN * (NH * HID)]; // [n][h*256+j]
__device__ __align__(16) float g_feats[(size_t)NH * NN * OUTD];   // [h][n][64]
__device__ float g_ssrc[NH * NN];  // f_src . aw[0:64]  (+ attn_b folded in)
__device__ float g_sdst[NH * NN];  // f_dst . aw[64:128]

// ---------------- idx dtype sniff (int64 vs canonicalized int32) ---------
__device__ __forceinline__ bool idx_is64(const int* p) {
    // values < 50000, so int64 storage has zero hi-words at odd int32 slots.
    return (p[1] | p[3] | p[5] | p[7]) == 0;
}
__device__ __forceinline__ int load_src(const void* idx, int e, bool is64) {
    return is64 ? (int)((const long long*)idx)[e] : ((const int*)idx)[e];
}
__device__ __forceinline__ int load_dst(const void* idx, int e, bool is64) {
    return is64 ? (int)((const long long*)idx)[NE + e] : ((const int*)idx)[NE + e];
}

// ---------------- CSR build ----------------
__global__ void k_zero() {
    int i = blockIdx.x * blockDim.x + threadIdx.x;
    if (i < NN) { g_deg[i] = 0; g_cursor[i] = 0; }
}

__global__ void k_hist(const void* __restrict__ idx) {
    bool is64 = idx_is64((const int*)idx);
    int e = blockIdx.x * blockDim.x + threadIdx.x;
    if (e < NE) atomicAdd(&g_deg[load_src(idx, e, is64)], 1);
}

__global__ void k_scan() {
    __shared__ int sm[1024];
    const int CH = 49;                       // 1024*49 = 50176 >= 50001
    int t = threadIdx.x;
    int base = t * CH;
    int s = 0;
    for (int i = 0; i < CH; i++) {
        int g = base + i;
        if (g < NN) s += g_deg[g];
    }
    sm[t] = s;
    __syncthreads();
    for (int off = 1; off < 1024; off <<= 1) {
        int v = (t >= off) ? sm[t - off] : 0;
        __syncthreads();
        sm[t] += v;
        __syncthreads();
    }
    int run = sm[t] - s;                     // exclusive prefix
    for (int i = 0; i < CH; i++) {
        int g = base + i;
        if (g <= NN) g_rowptr[g] = run;
        if (g < NN)  run += g_deg[g];
    }
}

__global__ void k_scatter(const void* __restrict__ idx, const float* __restrict__ elem) {
    bool is64 = idx_is64((const int*)idx);
    int e = blockIdx.x * blockDim.x + threadIdx.x;
    if (e < NE) {
        int s = load_src(idx, e, is64);
        int pos = g_rowptr[s] + atomicAdd(&g_cursor[s], 1);
        g_edst[pos]  = load_dst(idx, e, is64);
        g_eelem[pos] = elem[e];
    }
}

// ---------------- GEMM1: hidden = relu(x @ W1[h] + b1[h]) ----------------
// C tile 128x128, BK=16, 256 threads, 8x8 micro-tile.
__global__ __launch_bounds__(256) void k_gemm1(const float* __restrict__ X,
                                               const float* __restrict__ W1,
                                               const float* __restrict__ b1) {
    __shared__ float As[16][128 + 4];
    __shared__ float Bs[16][128];
    const int h  = blockIdx.z;
    const int m0 = blockIdx.x * 128;
    const int n0 = blockIdx.y * 128;           // column within the head (0 or 128)
    const float* B = W1 + (size_t)h * HID * INDIM; // [k][j] row-major 256x256

    const int tid  = threadIdx.x;
    const int tx   = tid & 15, ty = tid >> 4;
    const int arow = tid >> 2;                 // 0..63
    const int acol = (tid & 3) << 2;           // 0,4,8,12
    const int brow = tid >> 5;                 // 0..7
    const int bcol = (tid & 31) << 2;          // 0..124

    float acc[8][8];
#pragma unroll
    for (int i = 0; i < 8; i++)
#pragma unroll
        for (int j = 0; j < 8; j++) acc[i][j] = 0.f;

    for (int k0 = 0; k0 < INDIM; k0 += 16) {
#pragma unroll
        for (int r = 0; r < 2; r++) {
            int row = m0 + arow + r * 64;
            float4 v = make_float4(0.f, 0.f, 0.f, 0.f);
            if (row < NN) v = *(const float4*)(X + (size_t)row * INDIM + k0 + acol);
            As[acol + 0][arow + r * 64] = v.x;
            As[acol + 1][arow + r * 64] = v.y;
            As[acol + 2][arow + r * 64] = v.z;
            As[acol + 3][arow + r * 64] = v.w;
        }
#pragma unroll
        for (int r = 0; r < 2; r++) {
            int kr = k0 + brow + r * 8;
            *(float4*)&Bs[brow + r * 8][bcol] =
                *(const float4*)(B + (size_t)kr * HID + n0 + bcol);
        }
        __syncthreads();
#pragma unroll
        for (int k = 0; k < 16; k++) {
            float a[8], b[8];
#pragma unroll
            for (int i = 0; i < 8; i++) a[i] = As[k][ty * 8 + i];
#pragma unroll
            for (int j = 0; j < 8; j++) b[j] = Bs[k][tx * 8 + j];
#pragma unroll
            for (int i = 0; i < 8; i++)
#pragma unroll
                for (int j = 0; j < 8; j++)
                    acc[i][j] = fmaf(a[i], b[j], acc[i][j]);
        }
        __syncthreads();
    }

    const float* bias = b1 + h * HID + n0 + tx * 8;
    float bb[8];
#pragma unroll
    for (int j = 0; j < 8; j++) bb[j] = bias[j];
#pragma unroll
    for (int i = 0; i < 8; i++) {
        int row = m0 + ty * 8 + i;
        if (row >= NN) continue;
        float* crow = g_hidden + (size_t)row * (NH * HID) + h * HID + n0 + tx * 8;
#pragma unroll
        for (int j = 0; j < 8; j++) {
            float v = acc[i][j] + bb[j];
            crow[j] = v > 0.f ? v : 0.f;
        }
    }
}

// ---------------- GEMM2: feats = hidden @ W2[h] + b2[h] ----------------
// C tile 128x64, BK=16, 256 threads, 8x4 micro-tile.
__global__ __launch_bounds__(256) void k_gemm2(const float* __restrict__ W2,
                                               const float* __restrict__ b2) {
    __shared__ float As[16][128 + 4];
    __shared__ float Bs[16][64];
    const int h  = blockIdx.z;
    const int m0 = blockIdx.x * 128;
    const float* B = W2 + (size_t)h * HID * OUTD;   // 256x64 row-major

    const int tid  = threadIdx.x;
    const int tx   = tid & 15, ty = tid >> 4;
    const int arow = tid >> 2;
    const int acol = (tid & 3) << 2;
    const int brow = tid >> 4;                 // 0..15
    const int bcol = (tid & 15) << 2;          // 0..60

    float acc[8][4];
#pragma unroll
    for (int i = 0; i < 8; i++)
#pragma unroll
        for (int j = 0; j < 4; j++) acc[i][j] = 0.f;

    for (int k0 = 0; k0 < HID; k0 += 16) {
#pragma unroll
        for (int r = 0; r < 2; r++) {
            int row = m0 + arow + r * 64;
            float4 v = make_float4(0.f, 0.f, 0.f, 0.f);
            if (row < NN)
                v = *(const float4*)(g_hidden + (size_t)row * (NH * HID) + h * HID + k0 + acol);
            As[acol + 0][arow + r * 64] = v.x;
            As[acol + 1][arow + r * 64] = v.y;
            As[acol + 2][arow + r * 64] = v.z;
            As[acol + 3][arow + r * 64] = v.w;
        }
        *(float4*)&Bs[brow][bcol] = *(const float4*)(B + (size_t)(k0 + brow) * OUTD + bcol);
        __syncthreads();
#pragma unroll
        for (int k = 0; k < 16; k++) {
            float a[8], b[4];
#pragma unroll
            for (int i = 0; i < 8; i++) a[i] = As[k][ty * 8 + i];
#pragma unroll
            for (int j = 0; j < 4; j++) b[j] = Bs[k][tx * 4 + j];
#pragma unroll
            for (int i = 0; i < 8; i++)
#pragma unroll
                for (int j = 0; j < 4; j++)
                    acc[i][j] = fmaf(a[i], b[j], acc[i][j]);
        }
        __syncthreads();
    }

    float bb[4];
#pragma unroll
    for (int j = 0; j < 4; j++) bb[j] = b2[h * OUTD + tx * 4 + j];
#pragma unroll
    for (int i = 0; i < 8; i++) {
        int row = m0 + ty * 8 + i;
        if (row >= NN) continue;
        float4 v;
        v.x = acc[i][0] + bb[0];
        v.y = acc[i][1] + bb[1];
        v.z = acc[i][2] + bb[2];
        v.w = acc[i][3] + bb[3];
        *(float4*)(g_feats + ((size_t)h * NN + row) * OUTD + tx * 4) = v;
    }
}

// ---------------- per-node attention dot products ----------------
// s_src[h][n] = feats[h][n].aw[h][0:64] + attn_b[h];  s_dst[h][n] = feats.aw[h][64:128]
__global__ __launch_bounds__(256) void k_scores(const float* __restrict__ aw,
                                                const float* __restrict__ ab) {
    int lane = threadIdx.x & 31;
    int warp = threadIdx.x >> 5;
    int n = blockIdx.x * 8 + warp;
    int h = blockIdx.y;
    if (n >= NN) return;
    const float* f = g_feats + ((size_t)h * NN + n) * OUTD + 2 * lane;
    const float* w = aw + h * (2 * OUTD + 1);
    float s1 = f[0] * w[2 * lane]      + f[1] * w[2 * lane + 1];
    float s2 = f[0] * w[64 + 2 * lane] + f[1] * w[65 + 2 * lane];
#pragma unroll
    for (int o = 16; o; o >>= 1) {
        s1 += __shfl_xor_sync(0xffffffffu, s1, o);
        s2 += __shfl_xor_sync(0xffffffffu, s2, o);
    }
    if (lane == 0) {
        g_ssrc[h * NN + n] = s1 + ab[h];
        g_sdst[h * NN + n] = s2;
    }
}

// ---------------- edge softmax-aggregation: warp per (node, head) ----------------
__global__ __launch_bounds__(256) void k_pool(float* __restrict__ out,
                                              const float* __restrict__ aw) {
    int lane = threadIdx.x & 31;
    int gw = blockIdx.x * 8 + (threadIdx.x >> 5);
    if (gw >= NH * NN) return;
    int n = gw >> 2;
    int h = gw & 3;

    int s = g_rowptr[n];
    int e = g_rowptr[n + 1];
    float base = g_ssrc[h * NN + n];                 // includes attn_b
    float awe  = __ldg(&aw[h * (2 * OUTD + 1) + 2 * OUTD]);
    const float*  sd = g_sdst + (size_t)h * NN;
    const float2* f2 = (const float2*)(g_feats + (size_t)h * NN * OUTD);

    float ax = 0.f, ay = 0.f, wsum = 0.f;
    for (int i = s; i < e; i++) {
        int d    = g_edst[i];
        float sc = base + sd[d] + g_eelem[i] * awe;
        float w  = __expf(sc);                       // global shift cancels in ratio
        float2 f = f2[(size_t)d * 32 + lane];
        ax = fmaf(w, f.x, ax);
        ay = fmaf(w, f.y, ay);
        wsum += w;
    }
    float2 o;
    o.x = ax / wsum;
    o.y = ay / wsum;
    *(float2*)(out + (size_t)n * (NH * OUTD) + h * OUTD + 2 * lane) = o;
}

// ---------------- launch ----------------
extern "C" void kernel_launch(void* const* d_in, const int* in_sizes, int n_in,
                              void* d_out, int out_size) {
    const float* x    = (const float*)d_in[0];
    const void*  idx  = d_in[1];                 // int64 or int32, sniffed on-device
    const float* elem = (const float*)d_in[2];
    const float* W1   = (const float*)d_in[3];
    const float* b1   = (const float*)d_in[4];
    const float* W2   = (const float*)d_in[5];
    const float* b2   = (const float*)d_in[6];
    const float* aw   = (const float*)d_in[7];
    const float* ab   = (const float*)d_in[8];
    float* out = (float*)d_out;

    // CSR build (independent of GEMMs, same stream keeps ordering)
    k_zero   <<<(NN + 255) / 256, 256>>>();
    k_hist   <<<(NE + 255) / 256, 256>>>(idx);
    k_scan   <<<1, 1024>>>();
    k_scatter<<<(NE + 255) / 256, 256>>>(idx, elem);

    // MLP
    dim3 g1((NN + 127) / 128, HID / 128, NH);
    k_gemm1<<<g1, 256>>>(x, W1, b1);
    dim3 g2((NN + 127) / 128, 1, NH);
    k_gemm2<<<g2, 256>>>(W2, b2);

    // attention dots + aggregation
    dim3 gs((NN + 7) / 8, NH);
    k_scores<<<gs, 256>>>(aw, ab);
    k_pool  <<<(NH * NN + 7) / 8, 256>>>(out, aw);
}

// round 7
// speedup vs baseline: 1.7945x; 1.7945x over previous
#include <cuda_runtime.h>
#include <cuda_bf16.h>
#include <cstdint>
#include <cstddef>

#define NN 50000
#define NE 800000
#define INDIM 256
#define HID 256
#define OUTD 64
#define NH 4

#define SWZ(o) ((o) ^ (((o) >> 3) & 0x70))

// ---------------- device scratch (static allocation only) ----------------
__device__ int   g_deg[NN];
__device__ int   g_cursor[NN];
__device__ int   g_rowptr[NN + 1];
__device__ int   g_edst[NE];
__device__ float g_eelem[NE];
__device__ __align__(16) float g_feats[(size_t)NH * NN * OUTD];   // [h][n][64]
__device__ float g_ssrc[NH * NN];
__device__ float g_sdst[NH * NN];
// fragment-packed weights: [h][comp][kstep][nb2][lane][w] uint32 (bf16x2)
__device__ __align__(16) uint32_t g_b1pk[4 * 2 * 16 * 16 * 32 * 4];  // 262144 (1MB)
__device__ __align__(16) uint32_t g_b2pk[4 * 2 * 16 * 4 * 32 * 4];   // 65536 (256KB)

// ---------------- helpers ----------------
__device__ __forceinline__ uint32_t smem_u32(const void* p) {
    uint32_t a;
    asm("{ .reg .u64 t; cvta.to.shared.u64 t, %1; cvt.u32.u64 %0, t; }" : "=r"(a) : "l"(p));
    return a;
}
__device__ __forceinline__ void fsplit(float f, __nv_bfloat16& h, __nv_bfloat16& l) {
    h = __float2bfloat16(f);
    l = __float2bfloat16(f - __bfloat162float(h));
}
__device__ __forceinline__ uint32_t pk(__nv_bfloat16 a, __nv_bfloat16 b) {
    __nv_bfloat162 t = __halves2bfloat162(a, b);   // a -> low half
    return reinterpret_cast<uint32_t&>(t);
}
__device__ __forceinline__ void ldsm4(uint32_t* r, uint32_t addr) {
    asm volatile("ldmatrix.sync.aligned.m8n8.x4.shared.b16 {%0,%1,%2,%3}, [%4];"
                 : "=r"(r[0]), "=r"(r[1]), "=r"(r[2]), "=r"(r[3]) : "r"(addr));
}
__device__ __forceinline__ void mma16816(float* c, const uint32_t* a, uint32_t b0, uint32_t b1) {
    asm volatile("mma.sync.aligned.m16n8k16.row.col.f32.bf16.bf16.f32 "
                 "{%0,%1,%2,%3}, {%4,%5,%6,%7}, {%8,%9}, {%0,%1,%2,%3};"
                 : "+f"(c[0]), "+f"(c[1]), "+f"(c[2]), "+f"(c[3])
                 : "r"(a[0]), "r"(a[1]), "r"(a[2]), "r"(a[3]), "r"(b0), "r"(b1));
}

// ---------------- idx dtype sniff ----------------
__device__ __forceinline__ bool idx_is64(const int* p) {
    return (p[1] | p[3] | p[5] | p[7]) == 0;
}
__device__ __forceinline__ int load_src(const void* idx, int e, bool is64) {
    return is64 ? (int)((const long long*)idx)[e] : ((const int*)idx)[e];
}
__device__ __forceinline__ int load_dst(const void* idx, int e, bool is64) {
    return is64 ? (int)((const long long*)idx)[NE + e] : ((const int*)idx)[NE + e];
}

// ---------------- CSR build ----------------
__global__ void k_zero() {
    int i = blockIdx.x * blockDim.x + threadIdx.x;
    if (i < NN) { g_deg[i] = 0; g_cursor[i] = 0; }
}
__global__ void k_hist(const void* __restrict__ idx) {
    bool is64 = idx_is64((const int*)idx);
    int e = blockIdx.x * blockDim.x + threadIdx.x;
    if (e < NE) atomicAdd(&g_deg[load_src(idx, e, is64)], 1);
}
__global__ void k_scan() {
    __shared__ int sm[1024];
    const int CH = 49;
    int t = threadIdx.x;
    int base = t * CH, s = 0;
    for (int i = 0; i < CH; i++) { int g = base + i; if (g < NN) s += g_deg[g]; }
    sm[t] = s;
    __syncthreads();
    for (int off = 1; off < 1024; off <<= 1) {
        int v = (t >= off) ? sm[t - off] : 0;
        __syncthreads();
        sm[t] += v;
        __syncthreads();
    }
    int run = sm[t] - s;
    for (int i = 0; i < CH; i++) {
        int g = base + i;
        if (g <= NN) g_rowptr[g] = run;
        if (g < NN)  run += g_deg[g];
    }
}
__global__ void k_scatter(const void* __restrict__ idx, const float* __restrict__ elem) {
    bool is64 = idx_is64((const int*)idx);
    int e = blockIdx.x * blockDim.x + threadIdx.x;
    if (e < NE) {
        int s = load_src(idx, e, is64);
        int pos = g_rowptr[s] + atomicAdd(&g_cursor[s], 1);
        g_edst[pos]  = load_dst(idx, e, is64);
        g_eelem[pos] = elem[e];
    }
}

// ---------------- weight prep: transpose + split + fragment packing ----------------
// B fragment for mma row.col from W^T: lane holds n = nb2*16 + (w/2)*8 + lane/4,
// k = kstep*16 + (lane%4)*2 + (w%2)*8, packed as bf16 pair (k, k+1).
__global__ void k_prep(const float* __restrict__ W1, const float* __restrict__ W2) {
    int i = blockIdx.x * blockDim.x + threadIdx.x;
    if (i < 262144) {
        int h = i >> 16;
        int rem = i & 65535;
        int comp = rem >> 15;
        int rem2 = rem & 32767;
        int kstep = rem2 >> 11;
        int rem3 = rem2 & 2047;
        int nb2 = rem3 >> 7;
        int rem4 = rem3 & 127;
        int lane = rem4 >> 2;
        int w = rem4 & 3;
        int n = nb2 * 16 + ((w >> 1) << 3) + (lane >> 2);
        int k = (kstep << 4) + ((lane & 3) << 1) + ((w & 1) << 3);
        float f0 = W1[((h << 8) + k) * 256 + n];
        float f1 = W1[((h << 8) + k + 1) * 256 + n];
        __nv_bfloat16 h0, l0, h1, l1;
        fsplit(f0, h0, l0); fsplit(f1, h1, l1);
        g_b1pk[i] = comp ? pk(l0, l1) : pk(h0, h1);
    } else if (i < 262144 + 65536) {
        int j = i - 262144;
        int h = j >> 14;
        int rem = j & 16383;
        int comp = rem >> 13;
        int rem2 = rem & 8191;
        int kstep = rem2 >> 9;
        int rem3 = rem2 & 511;
        int nb2 = rem3 >> 7;
        int rem4 = rem3 & 127;
        int lane = rem4 >> 2;
        int w = rem4 & 3;
        int n = nb2 * 16 + ((w >> 1) << 3) + (lane >> 2);
        int k = (kstep << 4) + ((lane & 3) << 1) + ((w & 1) << 3);
        float f0 = W2[((h << 8) + k) * 64 + n];
        float f1 = W2[((h << 8) + k + 1) * 64 + n];
        __nv_bfloat16 h0, l0, h1, l1;
        fsplit(f0, h0, l0); fsplit(f1, h1, l1);
        g_b2pk[j] = comp ? pk(l0, l1) : pk(h0, h1);
    }
}

// ---------------- fused MLP: HMMA bf16x3, GEMM1 -> relu -> GEMM2 ----------------
// SMEM: A buffer, 2 comps x [kslab(4)][row(128)][64 bf16] 16KB tiles = 128KB total.
static constexpr uint32_t SM_COMP = 65536;
static constexpr uint32_t SM_TOT  = 131072;

__global__ __launch_bounds__(256, 1) void k_fused(const float* __restrict__ X,
                                                  const float* __restrict__ b1,
                                                  const float* __restrict__ b2) {
    extern __shared__ char smem[];
    const uint32_t sb = smem_u32(smem);
    const int tid  = threadIdx.x;
    const int lane = tid & 31;
    const int wid  = tid >> 5;
    const int h    = blockIdx.y;
    const int m0   = blockIdx.x * 128;

    // ldmatrix per-thread address pieces
    const int quad = lane >> 3;
    const uint32_t rowoff = ((quad & 1) << 3) | (lane & 7);
    const uint32_t kboff  = (quad >> 1) << 4;

    // ---- stage X split into SMEM ----
    {
        const int row = tid >> 1;
        const int kh  = (tid & 1) << 7;
        const bool rok = (m0 + row) < NN;
        const float* xr = X + (size_t)(m0 + row) * INDIM + kh;
#pragma unroll
        for (int c8 = 0; c8 < 16; c8++) {
            int kg = kh + c8 * 8;
            float4 v0, v1;
            if (rok) {
                v0 = *(const float4*)(xr + c8 * 8);
                v1 = *(const float4*)(xr + c8 * 8 + 4);
            } else {
                v0 = make_float4(0.f, 0.f, 0.f, 0.f);
                v1 = v0;
            }
            __nv_bfloat16 h0,l0,h1,l1,h2,l2,h3,l3,h4,l4,h5,l5,h6,l6,h7,l7;
            fsplit(v0.x, h0, l0); fsplit(v0.y, h1, l1);
            fsplit(v0.z, h2, l2); fsplit(v0.w, h3, l3);
            fsplit(v1.x, h4, l4); fsplit(v1.y, h5, l5);
            fsplit(v1.z, h6, l6); fsplit(v1.w, h7, l7);
            uint32_t off = ((uint32_t)(kg >> 6) * 16384u) + SWZ((uint32_t)((row << 7) | ((kg & 63) << 1)));
            *(uint4*)(smem + off)            = make_uint4(pk(h0,h1), pk(h2,h3), pk(h4,h5), pk(h6,h7));
            *(uint4*)(smem + SM_COMP + off)  = make_uint4(pk(l0,l1), pk(l2,l3), pk(l4,l5), pk(l6,l7));
        }
    }
    __syncthreads();

    // ---- GEMM1: C1[128x256] = A(128x256) @ W1, 3 split products ----
    const int mi = wid >> 2, ni = wid & 3;
    float acc[2][4][4][4];
#pragma unroll
    for (int a = 0; a < 2; a++)
#pragma unroll
        for (int b = 0; b < 4; b++)
#pragma unroll
            for (int c = 0; c < 4; c++)
#pragma unroll
                for (int d = 0; d < 4; d++) acc[a][b][c][d] = 0.f;

    const uint4* B1 = (const uint4*)g_b1pk;
#pragma unroll 1
    for (int combo = 0; combo < 3; combo++) {
        const int ac = (combo == 2) ? 1 : 0;
        const int bc = (combo == 1) ? 1 : 0;
        const uint4* bp = B1 + (size_t)((h * 2 + bc) * 16) * 512 + lane;
        const uint32_t abase = sb + ac * SM_COMP;
#pragma unroll 4
        for (int ks = 0; ks < 16; ks++) {
            uint4 bw0 = bp[ks * 512 + (ni * 2) * 32];
            uint4 bw1 = bp[ks * 512 + (ni * 2 + 1) * 32];
            uint4 bw2 = bp[ks * 512 + (8 + ni * 2) * 32];
            uint4 bw3 = bp[ks * 512 + (8 + ni * 2 + 1) * 32];
            uint32_t a[4][4];
            uint32_t kb = ((uint32_t)(ks & 3) << 5) | kboff;
            uint32_t slab = (uint32_t)(ks >> 2) * 16384u;
#pragma unroll
            for (int mf = 0; mf < 4; mf++) {
                uint32_t addr = abase + slab +
                    SWZ((uint32_t)(((mi * 64 + mf * 16 + rowoff) << 7)) | kb);
                ldsm4(a[mf], addr);
            }
#pragma unroll
            for (int mf = 0; mf < 4; mf++) {
                mma16816(acc[0][mf][0], a[mf], bw0.x, bw0.y);
                mma16816(acc[0][mf][1], a[mf], bw0.z, bw0.w);
                mma16816(acc[0][mf][2], a[mf], bw1.x, bw1.y);
                mma16816(acc[0][mf][3], a[mf], bw1.z, bw1.w);
                mma16816(acc[1][mf][0], a[mf], bw2.x, bw2.y);
                mma16816(acc[1][mf][1], a[mf], bw2.z, bw2.w);
                mma16816(acc[1][mf][2], a[mf], bw3.x, bw3.y);
                mma16816(acc[1][mf][3], a[mf], bw3.z, bw3.w);
            }
        }
    }
    __syncthreads();   // all GEMM1 reads of A done

    // ---- epilogue1: bias + relu + split, write hidden back into A buffer ----
#pragma unroll
    for (int nh = 0; nh < 2; nh++) {
#pragma unroll
        for (int nf = 0; nf < 4; nf++) {
            int n = nh * 128 + ni * 32 + nf * 8 + ((lane & 3) << 1);
            float bv0 = __ldg(&b1[(h << 8) + n]);
            float bv1 = __ldg(&b1[(h << 8) + n + 1]);
            uint32_t kslab = (uint32_t)(n >> 6) * 16384u;
            uint32_t cb = (uint32_t)(n & 63) << 1;
#pragma unroll
            for (int mf = 0; mf < 4; mf++) {
#pragma unroll
                for (int rr = 0; rr < 2; rr++) {
                    int row = mi * 64 + mf * 16 + (lane >> 2) + rr * 8;
                    float v0 = acc[nh][mf][nf][rr * 2]     + bv0;
                    float v1 = acc[nh][mf][nf][rr * 2 + 1] + bv1;
                    v0 = v0 > 0.f ? v0 : 0.f;
                    v1 = v1 > 0.f ? v1 : 0.f;
                    __nv_bfloat16 h0, l0, h1, l1;
                    fsplit(v0, h0, l0); fsplit(v1, h1, l1);
                    uint32_t off = kslab + SWZ((uint32_t)((row << 7)) | cb);
                    *(uint32_t*)(smem + off)           = pk(h0, h1);
                    *(uint32_t*)(smem + SM_COMP + off) = pk(l0, l1);
                }
            }
        }
    }
    __syncthreads();

    // ---- GEMM2: C2[128x64] = hidden(128x256) @ W2, 3 split products ----
    const int mi2 = wid >> 2, ni2 = wid & 3;
    float c2[4][2][4];
#pragma unroll
    for (int a = 0; a < 4; a++)
#pragma unroll
        for (int b = 0; b < 2; b++)
#pragma unroll
            for (int c = 0; c < 4; c++) c2[a][b][c] = 0.f;

    const uint4* B2 = (const uint4*)g_b2pk;
#pragma unroll 1
    for (int combo = 0; combo < 3; combo++) {
        const int ac = (combo == 2) ? 1 : 0;
        const int bc = (combo == 1) ? 1 : 0;
        const uint4* bp = B2 + (size_t)((h * 2 + bc) * 16) * 128 + ni2 * 32 + lane;
        const uint32_t abase = sb + ac * SM_COMP;
#pragma unroll 4
        for (int ks = 0; ks < 16; ks++) {
            uint4 bw = bp[ks * 128];
            uint32_t a[4][4];
            uint32_t kb = ((uint32_t)(ks & 3) << 5) | kboff;
            uint32_t slab = (uint32_t)(ks >> 2) * 16384u;
#pragma unroll
            for (int mf = 0; mf < 4; mf++) {
                uint32_t addr = abase + slab +
                    SWZ((uint32_t)(((mi2 * 64 + mf * 16 + rowoff) << 7)) | kb);
                ldsm4(a[mf], addr);
            }
#pragma unroll
            for (int mf = 0; mf < 4; mf++) {
                mma16816(c2[mf][0], a[mf], bw.x, bw.y);
                mma16816(c2[mf][1], a[mf], bw.z, bw.w);
            }
        }
    }

    // ---- final: bias + store feats ----
#pragma unroll
    for (int nf = 0; nf < 2; nf++) {
        int n = ni2 * 16 + nf * 8 + ((lane & 3) << 1);
        float bv0 = __ldg(&b2[(h << 6) + n]);
        float bv1 = __ldg(&b2[(h << 6) + n + 1]);
#pragma unroll
        for (int mf = 0; mf < 4; mf++) {
#pragma unroll
            for (int rr = 0; rr < 2; rr++) {
                int row = m0 + mi2 * 64 + mf * 16 + (lane >> 2) + rr * 8;
                if (row < NN) {
                    float2 o;
                    o.x = c2[mf][nf][rr * 2]     + bv0;
                    o.y = c2[mf][nf][rr * 2 + 1] + bv1;
                    *(float2*)(g_feats + ((size_t)h * NN + row) * OUTD + n) = o;
                }
            }
        }
    }
}

// ---------------- per-node attention dot products ----------------
__global__ __launch_bounds__(256) void k_scores(const float* __restrict__ aw,
                                                const float* __restrict__ ab) {
    int lane = threadIdx.x & 31;
    int warp = threadIdx.x >> 5;
    int n = blockIdx.x * 8 + warp;
    int h = blockIdx.y;
    if (n >= NN) return;
    const float* f = g_feats + ((size_t)h * NN + n) * OUTD + 2 * lane;
    const float* w = aw + h * (2 * OUTD + 1);
    float s1 = f[0] * w[2 * lane]      + f[1] * w[2 * lane + 1];
    float s2 = f[0] * w[64 + 2 * lane] + f[1] * w[65 + 2 * lane];
#pragma unroll
    for (int o = 16; o; o >>= 1) {
        s1 += __shfl_xor_sync(0xffffffffu, s1, o);
        s2 += __shfl_xor_sync(0xffffffffu, s2, o);
    }
    if (lane == 0) {
        g_ssrc[h * NN + n] = s1 + ab[h];
        g_sdst[h * NN + n] = s2;
    }
}

// ---------------- edge softmax-aggregation: warp per (node, head) ----------------
__global__ __launch_bounds__(256) void k_pool(float* __restrict__ out,
                                              const float* __restrict__ aw) {
    int lane = threadIdx.x & 31;
    int gw = blockIdx.x * 8 + (threadIdx.x >> 5);
    if (gw >= NH * NN) return;
    int n = gw >> 2;
    int h = gw & 3;

    int s = g_rowptr[n];
    int e = g_rowptr[n + 1];
    float base = g_ssrc[h * NN + n];
    float awe  = __ldg(&aw[h * (2 * OUTD + 1) + 2 * OUTD]);
    const float*  sd = g_sdst + (size_t)h * NN;
    const float2* f2 = (const float2*)(g_feats + (size_t)h * NN * OUTD);

    float ax = 0.f, ay = 0.f, wsum = 0.f;
    for (int i = s; i < e; i++) {
        int d    = g_edst[i];
        float sc = base + sd[d] + g_eelem[i] * awe;
        float w  = __expf(sc);
        float2 f = f2[(size_t)d * 32 + lane];
        ax = fmaf(w, f.x, ax);
        ay = fmaf(w, f.y, ay);
        wsum += w;
    }
    float2 o;
    o.x = ax / wsum;
    o.y = ay / wsum;
    *(float2*)(out + (size_t)n * (NH * OUTD) + h * OUTD + 2 * lane) = o;
}

// ---------------- launch ----------------
extern "C" void kernel_launch(void* const* d_in, const int* in_sizes, int n_in,
                              void* d_out, int out_size) {
    const float* x    = (const float*)d_in[0];
    const void*  idx  = d_in[1];
    const float* elem = (const float*)d_in[2];
    const float* W1   = (const float*)d_in[3];
    const float* b1   = (const float*)d_in[4];
    const float* W2   = (const float*)d_in[5];
    const float* b2   = (const float*)d_in[6];
    const float* aw   = (const float*)d_in[7];
    const float* ab   = (const float*)d_in[8];
    float* out = (float*)d_out;

    cudaFuncSetAttribute(k_fused, cudaFuncAttributeMaxDynamicSharedMemorySize, SM_TOT);

    // CSR build
    k_zero   <<<(NN + 255) / 256, 256>>>();
    k_hist   <<<(NE + 255) / 256, 256>>>(idx);
    k_scan   <<<1, 1024>>>();
    k_scatter<<<(NE + 255) / 256, 256>>>(idx, elem);

    // weight prep (transpose + bf16 split + fragment pack)
    k_prep<<<(262144 + 65536 + 255) / 256, 256>>>(W1, W2);

    // fused MLP
    dim3 gf((NN + 127) / 128, NH);
    k_fused<<<gf, 256, SM_TOT>>>(x, b1, b2);

    // attention dots + aggregation
    dim3 gs((NN + 7) / 8, NH);
    k_scores<<<gs, 256>>>(aw, ab);
    k_pool  <<<(NH * NN + 7) / 8, 256>>>(out, aw);
}

// round 8
// speedup vs baseline: 1.9226x; 1.0713x over previous
#include <cuda_runtime.h>
#include <cuda_bf16.h>
#include <cstdint>
#include <cstddef>

#define NN 50000
#define NE 800000
#define INDIM 256
#define HID 256
#define OUTD 64
#define NH 4

#define SWZ(o) ((o) ^ (((o) >> 3) & 0x70))

// ---------------- device scratch (static allocation only) ----------------
__device__ int   g_deg[NN];
__device__ int   g_cursor[NN];
__device__ int   g_rowptr[NN + 1];
__device__ int   g_edst[NE];
__device__ float g_eelem[NE];
__device__ __align__(16) float g_feats[(size_t)NH * NN * OUTD];   // [h][n][64]
__device__ float g_ssrc[NH * NN];
__device__ float g_sdst[NH * NN];
// fragment-packed weights: [h][comp][kstep][nb2][lane][w] uint32 (bf16x2)
__device__ __align__(16) uint32_t g_b1pk[4 * 2 * 16 * 16 * 32 * 4];  // 1MB
__device__ __align__(16) uint32_t g_b2pk[4 * 2 * 16 * 4 * 32 * 4];   // 256KB

// ---------------- helpers ----------------
__device__ __forceinline__ uint32_t smem_u32(const void* p) {
    uint32_t a;
    asm("{ .reg .u64 t; cvta.to.shared.u64 t, %1; cvt.u32.u64 %0, t; }" : "=r"(a) : "l"(p));
    return a;
}
__device__ __forceinline__ void fsplit(float f, __nv_bfloat16& h, __nv_bfloat16& l) {
    h = __float2bfloat16(f);
    l = __float2bfloat16(f - __bfloat162float(h));
}
__device__ __forceinline__ uint32_t pk(__nv_bfloat16 a, __nv_bfloat16 b) {
    __nv_bfloat162 t = __halves2bfloat162(a, b);
    return reinterpret_cast<uint32_t&>(t);
}
__device__ __forceinline__ void ldsm4(uint32_t* r, uint32_t addr) {
    asm volatile("ldmatrix.sync.aligned.m8n8.x4.shared.b16 {%0,%1,%2,%3}, [%4];"
                 : "=r"(r[0]), "=r"(r[1]), "=r"(r[2]), "=r"(r[3]) : "r"(addr));
}
__device__ __forceinline__ void mma16816(float* c, const uint32_t* a, uint32_t b0, uint32_t b1) {
    asm volatile("mma.sync.aligned.m16n8k16.row.col.f32.bf16.bf16.f32 "
                 "{%0,%1,%2,%3}, {%4,%5,%6,%7}, {%8,%9}, {%0,%1,%2,%3};"
                 : "+f"(c[0]), "+f"(c[1]), "+f"(c[2]), "+f"(c[3])
                 : "r"(a[0]), "r"(a[1]), "r"(a[2]), "r"(a[3]), "r"(b0), "r"(b1));
}

// ---------------- idx dtype sniff ----------------
__device__ __forceinline__ bool idx_is64(const int* p) {
    return (p[1] | p[3] | p[5] | p[7]) == 0;
}
__device__ __forceinline__ int load_src(const void* idx, int e, bool is64) {
    return is64 ? (int)((const long long*)idx)[e] : ((const int*)idx)[e];
}
__device__ __forceinline__ int load_dst(const void* idx, int e, bool is64) {
    return is64 ? (int)((const long long*)idx)[NE + e] : ((const int*)idx)[NE + e];
}

// ---------------- CSR build ----------------
__global__ void k_zero() {
    int i = blockIdx.x * blockDim.x + threadIdx.x;
    if (i < NN) { g_deg[i] = 0; g_cursor[i] = 0; }
}
__global__ void k_hist(const void* __restrict__ idx) {
    bool is64 = idx_is64((const int*)idx);
    int e = blockIdx.x * blockDim.x + threadIdx.x;
    if (e < NE) atomicAdd(&g_deg[load_src(idx, e, is64)], 1);
}
__global__ void k_scan() {
    __shared__ int sm[1024];
    const int CH = 49;
    int t = threadIdx.x;
    int base = t * CH, s = 0;
    for (int i = 0; i < CH; i++) { int g = base + i; if (g < NN) s += g_deg[g]; }
    sm[t] = s;
    __syncthreads();
    for (int off = 1; off < 1024; off <<= 1) {
        int v = (t >= off) ? sm[t - off] : 0;
        __syncthreads();
        sm[t] += v;
        __syncthreads();
    }
    int run = sm[t] - s;
    for (int i = 0; i < CH; i++) {
        int g = base + i;
        if (g <= NN) g_rowptr[g] = run;
        if (g < NN)  run += g_deg[g];
    }
}
__global__ void k_scatter(const void* __restrict__ idx, const float* __restrict__ elem) {
    bool is64 = idx_is64((const int*)idx);
    int e = blockIdx.x * blockDim.x + threadIdx.x;
    if (e < NE) {
        int s = load_src(idx, e, is64);
        int pos = g_rowptr[s] + atomicAdd(&g_cursor[s], 1);
        g_edst[pos]  = load_dst(idx, e, is64);
        g_eelem[pos] = elem[e];
    }
}

// ---------------- weight prep: transpose + split + fragment packing ----------------
__global__ void k_prep(const float* __restrict__ W1, const float* __restrict__ W2) {
    int i = blockIdx.x * blockDim.x + threadIdx.x;
    if (i < 262144) {
        int h = i >> 16;
        int rem = i & 65535;
        int comp = rem >> 15;
        int rem2 = rem & 32767;
        int kstep = rem2 >> 11;
        int rem3 = rem2 & 2047;
        int nb2 = rem3 >> 7;
        int rem4 = rem3 & 127;
        int lane = rem4 >> 2;
        int w = rem4 & 3;
        int n = nb2 * 16 + ((w >> 1) << 3) + (lane >> 2);
        int k = (kstep << 4) + ((lane & 3) << 1) + ((w & 1) << 3);
        float f0 = W1[((h << 8) + k) * 256 + n];
        float f1 = W1[((h << 8) + k + 1) * 256 + n];
        __nv_bfloat16 h0, l0, h1, l1;
        fsplit(f0, h0, l0); fsplit(f1, h1, l1);
        g_b1pk[i] = comp ? pk(l0, l1) : pk(h0, h1);
    } else if (i < 262144 + 65536) {
        int j = i - 262144;
        int h = j >> 14;
        int rem = j & 16383;
        int comp = rem >> 13;
        int rem2 = rem & 8191;
        int kstep = rem2 >> 9;
        int rem3 = rem2 & 511;
        int nb2 = rem3 >> 7;
        int rem4 = rem3 & 127;
        int lane = rem4 >> 2;
        int w = rem4 & 3;
        int n = nb2 * 16 + ((w >> 1) << 3) + (lane >> 2);
        int k = (kstep << 4) + ((lane & 3) << 1) + ((w & 1) << 3);
        float f0 = W2[((h << 8) + k) * 64 + n];
        float f1 = W2[((h << 8) + k + 1) * 64 + n];
        __nv_bfloat16 h0, l0, h1, l1;
        fsplit(f0, h0, l0); fsplit(f1, h1, l1);
        g_b2pk[j] = comp ? pk(l0, l1) : pk(h0, h1);
    }
}

// ---------------- fused MLP: HMMA bf16x3, M=64 tiles, 2 CTAs/SM ----------------
// SMEM: 2 comps x [kslab(4)][row(64)][64 bf16] 8KB slabs = 64KB total.
static constexpr uint32_t SM_COMP = 32768;
static constexpr uint32_t SM_TOT  = 65536;

__global__ __launch_bounds__(256, 2) void k_fused(const float* __restrict__ X,
                                                  const float* __restrict__ b1,
                                                  const float* __restrict__ b2) {
    extern __shared__ char smem[];
    const uint32_t sb = smem_u32(smem);
    const int tid  = threadIdx.x;
    const int lane = tid & 31;
    const int wid  = tid >> 5;
    const int h    = blockIdx.y;
    const int m0   = blockIdx.x * 64;

    const int quad = lane >> 3;
    const uint32_t rowoff = ((quad & 1) << 3) | (lane & 7);
    const uint32_t kboff  = (quad >> 1) << 4;

    // ---- stage X split into SMEM: 64 rows x 256 cols, 4 threads/row ----
    {
        const int row = tid >> 2;                // 0..63
        const int kh  = (tid & 3) << 6;          // 0,64,128,192
        const bool rok = (m0 + row) < NN;
        const float* xr = X + (size_t)(m0 + row) * INDIM + kh;
        const uint32_t slab = (uint32_t)(kh >> 6) * 8192u;
#pragma unroll
        for (int c8 = 0; c8 < 8; c8++) {
            float4 v0, v1;
            if (rok) {
                v0 = *(const float4*)(xr + c8 * 8);
                v1 = *(const float4*)(xr + c8 * 8 + 4);
            } else {
                v0 = make_float4(0.f, 0.f, 0.f, 0.f);
                v1 = v0;
            }
            __nv_bfloat16 h0,l0,h1,l1,h2,l2,h3,l3,h4,l4,h5,l5,h6,l6,h7,l7;
            fsplit(v0.x, h0, l0); fsplit(v0.y, h1, l1);
            fsplit(v0.z, h2, l2); fsplit(v0.w, h3, l3);
            fsplit(v1.x, h4, l4); fsplit(v1.y, h5, l5);
            fsplit(v1.z, h6, l6); fsplit(v1.w, h7, l7);
            uint32_t off = slab + SWZ((uint32_t)((row << 7) | (c8 << 4)));
            *(uint4*)(smem + off)           = make_uint4(pk(h0,h1), pk(h2,h3), pk(h4,h5), pk(h6,h7));
            *(uint4*)(smem + SM_COMP + off) = make_uint4(pk(l0,l1), pk(l2,l3), pk(l4,l5), pk(l6,l7));
        }
    }
    __syncthreads();

    // ---- GEMM1: C1[64x256] = A(64x256) @ W1, merged 3-product loop ----
    const int mi = wid >> 2, ni = wid & 3;       // warp tile: 32 rows x 64 cols
    float acc[2][8][4];
#pragma unroll
    for (int a = 0; a < 2; a++)
#pragma unroll
        for (int b = 0; b < 8; b++)
#pragma unroll
            for (int c = 0; c < 4; c++) acc[a][b][c] = 0.f;

    {
        const uint4* bhi = (const uint4*)g_b1pk + (size_t)(h * 2 + 0) * 8192 + lane;
        const uint4* blo = (const uint4*)g_b1pk + (size_t)(h * 2 + 1) * 8192 + lane;
#pragma unroll 2
        for (int ks = 0; ks < 16; ks++) {
            uint4 bh[4], bl[4];
#pragma unroll
            for (int q = 0; q < 4; q++) {
                bh[q] = bhi[ks * 512 + (ni * 4 + q) * 32];
                bl[q] = blo[ks * 512 + (ni * 4 + q) * 32];
            }
            const uint32_t kb = ((uint32_t)(ks & 3) << 5) | kboff;
            const uint32_t slab = (uint32_t)(ks >> 2) * 8192u;
            uint32_t a[2][4];
#pragma unroll
            for (int mf = 0; mf < 2; mf++)
                ldsm4(a[mf], sb + slab + SWZ((uint32_t)(((mi * 32 + mf * 16 + rowoff) << 7)) | kb));
#pragma unroll
            for (int mf = 0; mf < 2; mf++)
#pragma unroll
                for (int q = 0; q < 4; q++) {
                    mma16816(acc[mf][q * 2 + 0], a[mf], bh[q].x, bh[q].y);
                    mma16816(acc[mf][q * 2 + 1], a[mf], bh[q].z, bh[q].w);
                }
#pragma unroll
            for (int mf = 0; mf < 2; mf++)
#pragma unroll
                for (int q = 0; q < 4; q++) {
                    mma16816(acc[mf][q * 2 + 0], a[mf], bl[q].x, bl[q].y);
                    mma16816(acc[mf][q * 2 + 1], a[mf], bl[q].z, bl[q].w);
                }
#pragma unroll
            for (int mf = 0; mf < 2; mf++)
                ldsm4(a[mf], sb + SM_COMP + slab + SWZ((uint32_t)(((mi * 32 + mf * 16 + rowoff) << 7)) | kb));
#pragma unroll
            for (int mf = 0; mf < 2; mf++)
#pragma unroll
                for (int q = 0; q < 4; q++) {
                    mma16816(acc[mf][q * 2 + 0], a[mf], bh[q].x, bh[q].y);
                    mma16816(acc[mf][q * 2 + 1], a[mf], bh[q].z, bh[q].w);
                }
        }
    }
    __syncthreads();   // all GEMM1 reads of A done

    // ---- epilogue1: bias + relu + split, write hidden back into A buffer ----
#pragma unroll
    for (int j = 0; j < 8; j++) {
        int n = ni * 64 + (j >> 1) * 16 + (j & 1) * 8 + ((lane & 3) << 1);
        float bv0 = __ldg(&b1[(h << 8) + n]);
        float bv1 = __ldg(&b1[(h << 8) + n + 1]);
        uint32_t kslab = (uint32_t)(n >> 6) * 8192u;
        uint32_t cb = (uint32_t)(n & 63) << 1;
#pragma unroll
        for (int mf = 0; mf < 2; mf++) {
#pragma unroll
            for (int rr = 0; rr < 2; rr++) {
                int row = mi * 32 + mf * 16 + (lane >> 2) + rr * 8;
                float v0 = acc[mf][j][rr * 2]     + bv0;
                float v1 = acc[mf][j][rr * 2 + 1] + bv1;
                v0 = v0 > 0.f ? v0 : 0.f;
                v1 = v1 > 0.f ? v1 : 0.f;
                __nv_bfloat16 h0, l0, h1, l1;
                fsplit(v0, h0, l0); fsplit(v1, h1, l1);
                uint32_t off = kslab + SWZ((uint32_t)((row << 7)) | cb);
                *(uint32_t*)(smem + off)           = pk(h0, h1);
                *(uint32_t*)(smem + SM_COMP + off) = pk(l0, l1);
            }
        }
    }
    __syncthreads();

    // ---- GEMM2: C2[64x64] = hidden(64x256) @ W2, merged loop ----
    float c2[2][2][4];
#pragma unroll
    for (int a = 0; a < 2; a++)
#pragma unroll
        for (int b = 0; b < 2; b++)
#pragma unroll
            for (int c = 0; c < 4; c++) c2[a][b][c] = 0.f;

    {
        const uint4* bhi = (const uint4*)g_b2pk + (size_t)(h * 2 + 0) * 2048 + ni * 32 + lane;
        const uint4* blo = (const uint4*)g_b2pk + (size_t)(h * 2 + 1) * 2048 + ni * 32 + lane;
#pragma unroll 4
        for (int ks = 0; ks < 16; ks++) {
            uint4 bh = bhi[ks * 128];
            uint4 bl = blo[ks * 128];
            const uint32_t kb = ((uint32_t)(ks & 3) << 5) | kboff;
            const uint32_t slab = (uint32_t)(ks >> 2) * 8192u;
            uint32_t a[2][4];
#pragma unroll
            for (int mf = 0; mf < 2; mf++)
                ldsm4(a[mf], sb + slab + SWZ((uint32_t)(((mi * 32 + mf * 16 + rowoff) << 7)) | kb));
#pragma unroll
            for (int mf = 0; mf < 2; mf++) {
                mma16816(c2[mf][0], a[mf], bh.x, bh.y);
                mma16816(c2[mf][1], a[mf], bh.z, bh.w);
                mma16816(c2[mf][0], a[mf], bl.x, bl.y);
                mma16816(c2[mf][1], a[mf], bl.z, bl.w);
            }
#pragma unroll
            for (int mf = 0; mf < 2; mf++)
                ldsm4(a[mf], sb + SM_COMP + slab + SWZ((uint32_t)(((mi * 32 + mf * 16 + rowoff) << 7)) | kb));
#pragma unroll
            for (int mf = 0; mf < 2; mf++) {
                mma16816(c2[mf][0], a[mf], bh.x, bh.y);
                mma16816(c2[mf][1], a[mf], bh.z, bh.w);
            }
        }
    }

    // ---- final: bias + store feats ----
#pragma unroll
    for (int j = 0; j < 2; j++) {
        int n = ni * 16 + j * 8 + ((lane & 3) << 1);
        float bv0 = __ldg(&b2[(h << 6) + n]);
        float bv1 = __ldg(&b2[(h << 6) + n + 1]);
#pragma unroll
        for (int mf = 0; mf < 2; mf++) {
#pragma unroll
            for (int rr = 0; rr < 2; rr++) {
                int row = m0 + mi * 32 + mf * 16 + (lane >> 2) + rr * 8;
                if (row < NN) {
                    float2 o;
                    o.x = c2[mf][j][rr * 2]     + bv0;
                    o.y = c2[mf][j][rr * 2 + 1] + bv1;
                    *(float2*)(g_feats + ((size_t)h * NN + row) * OUTD + n) = o;
                }
            }
        }
    }
}

// ---------------- per-node attention dot products ----------------
__global__ __launch_bounds__(256) void k_scores(const float* __restrict__ aw,
                                                const float* __restrict__ ab) {
    int lane = threadIdx.x & 31;
    int warp = threadIdx.x >> 5;
    int n = blockIdx.x * 8 + warp;
    int h = blockIdx.y;
    if (n >= NN) return;
    const float* f = g_feats + ((size_t)h * NN + n) * OUTD + 2 * lane;
    const float* w = aw + h * (2 * OUTD + 1);
    float s1 = f[0] * w[2 * lane]      + f[1] * w[2 * lane + 1];
    float s2 = f[0] * w[64 + 2 * lane] + f[1] * w[65 + 2 * lane];
#pragma unroll
    for (int o = 16; o; o >>= 1) {
        s1 += __shfl_xor_sync(0xffffffffu, s1, o);
        s2 += __shfl_xor_sync(0xffffffffu, s2, o);
    }
    if (lane == 0) {
        g_ssrc[h * NN + n] = s1 + ab[h];
        g_sdst[h * NN + n] = s2;
    }
}

// ---------------- edge softmax-aggregation: warp per (node, head) ----------------
__global__ __launch_bounds__(256) void k_pool(float* __restrict__ out,
                                              const float* __restrict__ aw) {
    int lane = threadIdx.x & 31;
    int gw = blockIdx.x * 8 + (threadIdx.x >> 5);
    if (gw >= NH * NN) return;
    int n = gw >> 2;
    int h = gw & 3;

    int s = g_rowptr[n];
    int e = g_rowptr[n + 1];
    float base = g_ssrc[h * NN + n];
    float awe  = __ldg(&aw[h * (2 * OUTD + 1) + 2 * OUTD]);
    const float*  sd = g_sdst + (size_t)h * NN;
    const float2* f2 = (const float2*)(g_feats + (size_t)h * NN * OUTD);

    float ax = 0.f, ay = 0.f, wsum = 0.f;
    for (int i = s; i < e; i++) {
        int d    = g_edst[i];
        float sc = base + sd[d] + g_eelem[i] * awe;
        float w  = __expf(sc);
        float2 f = f2[(size_t)d * 32 + lane];
        ax = fmaf(w, f.x, ax);
        ay = fmaf(w, f.y, ay);
        wsum += w;
    }
    float2 o;
    o.x = ax / wsum;
    o.y = ay / wsum;
    *(float2*)(out + (size_t)n * (NH * OUTD) + h * OUTD + 2 * lane) = o;
}

// ---------------- launch ----------------
extern "C" void kernel_launch(void* const* d_in, const int* in_sizes, int n_in,
                              void* d_out, int out_size) {
    const float* x    = (const float*)d_in[0];
    const void*  idx  = d_in[1];
    const float* elem = (const float*)d_in[2];
    const float* W1   = (const float*)d_in[3];
    const float* b1   = (const float*)d_in[4];
    const float* W2   = (const float*)d_in[5];
    const float* b2   = (const float*)d_in[6];
    const float* aw   = (const float*)d_in[7];
    const float* ab   = (const float*)d_in[8];
    float* out = (float*)d_out;

    cudaFuncSetAttribute(k_fused, cudaFuncAttributeMaxDynamicSharedMemorySize, SM_TOT);

    // CSR build
    k_zero   <<<(NN + 255) / 256, 256>>>();
    k_hist   <<<(NE + 255) / 256, 256>>>(idx);
    k_scan   <<<1, 1024>>>();
    k_scatter<<<(NE + 255) / 256, 256>>>(idx, elem);

    // weight prep
    k_prep<<<(262144 + 65536 + 255) / 256, 256>>>(W1, W2);

    // fused MLP (M=64 tiles, 2 CTAs/SM)
    dim3 gf((NN + 63) / 64, NH);
    k_fused<<<gf, 256, SM_TOT>>>(x, b1, b2);

    // attention dots + aggregation
    dim3 gs((NN + 7) / 8, NH);
    k_scores<<<gs, 256>>>(aw, ab);
    k_pool  <<<(NH * NN + 7) / 8, 256>>>(out, aw);
}

// round 9
// speedup vs baseline: 2.2616x; 1.1764x over previous
#include <cuda_runtime.h>
#include <cuda_fp16.h>
#include <cstdint>
#include <cstddef>

#define NN 50000
#define NE 800000
#define INDIM 256
#define HID 256
#define OUTD 64
#define NH 4

#define SWZ(o) ((o) ^ (((o) >> 3) & 0x70))

// ---------------- device scratch (static allocation only) ----------------
__device__ int   g_deg[NN];
__device__ int   g_cursor[NN];
__device__ int   g_rowptr[NN + 1];
__device__ int   g_edst[NE];
__device__ float g_eelem[NE];
__device__ __align__(16) __half g_featsh[(size_t)NH * NN * OUTD];  // [h][n][64] fp16
__device__ float g_ssrc[NH * NN];
__device__ float g_sdst[NH * NN];
// fragment-packed fp16 weights: [h][kstep][nb2][lane][w] uint32 (fp16x2)
__device__ __align__(16) uint32_t g_b1pk[4 * 16 * 16 * 32 * 4];  // 512KB
__device__ __align__(16) uint32_t g_b2pk[4 * 16 * 4 * 32 * 4];   // 128KB

// ---------------- helpers ----------------
__device__ __forceinline__ uint32_t smem_u32(const void* p) {
    uint32_t a;
    asm("{ .reg .u64 t; cvta.to.shared.u64 t, %1; cvt.u32.u64 %0, t; }" : "=r"(a) : "l"(p));
    return a;
}
__device__ __forceinline__ void fsplit(float f, __half& h, __half& l) {
    h = __float2half_rn(f);
    l = __float2half_rn(f - __half2float(h));
}
__device__ __forceinline__ uint32_t pk(__half a, __half b) {
    __half2 t = __halves2half2(a, b);   // a -> low half
    return reinterpret_cast<uint32_t&>(t);
}
__device__ __forceinline__ void ldsm4(uint32_t* r, uint32_t addr) {
    asm volatile("ldmatrix.sync.aligned.m8n8.x4.shared.b16 {%0,%1,%2,%3}, [%4];"
                 : "=r"(r[0]), "=r"(r[1]), "=r"(r[2]), "=r"(r[3]) : "r"(addr));
}
__device__ __forceinline__ void mma16816(float* c, const uint32_t* a, uint32_t b0, uint32_t b1) {
    asm volatile("mma.sync.aligned.m16n8k16.row.col.f32.f16.f16.f32 "
                 "{%0,%1,%2,%3}, {%4,%5,%6,%7}, {%8,%9}, {%0,%1,%2,%3};"
                 : "+f"(c[0]), "+f"(c[1]), "+f"(c[2]), "+f"(c[3])
                 : "r"(a[0]), "r"(a[1]), "r"(a[2]), "r"(a[3]), "r"(b0), "r"(b1));
}

// ---------------- idx dtype sniff ----------------
__device__ __forceinline__ bool idx_is64(const int* p) {
    return (p[1] | p[3] | p[5] | p[7]) == 0;
}
__device__ __forceinline__ int load_src(const void* idx, int e, bool is64) {
    return is64 ? (int)((const long long*)idx)[e] : ((const int*)idx)[e];
}
__device__ __forceinline__ int load_dst(const void* idx, int e, bool is64) {
    return is64 ? (int)((const long long*)idx)[NE + e] : ((const int*)idx)[NE + e];
}

// ---------------- CSR build ----------------
__global__ void k_zero() {
    int i = blockIdx.x * blockDim.x + threadIdx.x;
    if (i < NN) { g_deg[i] = 0; g_cursor[i] = 0; }
}
__global__ void k_hist(const void* __restrict__ idx) {
    bool is64 = idx_is64((const int*)idx);
    int e = blockIdx.x * blockDim.x + threadIdx.x;
    if (e < NE) atomicAdd(&g_deg[load_src(idx, e, is64)], 1);
}
__global__ void k_scan() {
    __shared__ int sm[1024];
    const int CH = 49;
    int t = threadIdx.x;
    int base = t * CH, s = 0;
    for (int i = 0; i < CH; i++) { int g = base + i; if (g < NN) s += g_deg[g]; }
    sm[t] = s;
    __syncthreads();
    for (int off = 1; off < 1024; off <<= 1) {
        int v = (t >= off) ? sm[t - off] : 0;
        __syncthreads();
        sm[t] += v;
        __syncthreads();
    }
    int run = sm[t] - s;
    for (int i = 0; i < CH; i++) {
        int g = base + i;
        if (g <= NN) g_rowptr[g] = run;
        if (g < NN)  run += g_deg[g];
    }
}
__global__ void k_scatter(const void* __restrict__ idx, const float* __restrict__ elem) {
    bool is64 = idx_is64((const int*)idx);
    int e = blockIdx.x * blockDim.x + threadIdx.x;
    if (e < NE) {
        int s = load_src(idx, e, is64);
        int pos = g_rowptr[s] + atomicAdd(&g_cursor[s], 1);
        g_edst[pos]  = load_dst(idx, e, is64);
        g_eelem[pos] = elem[e];
    }
}

// ---------------- weight prep: transpose + fp16 + fragment packing ----------------
// B fragment for mma row.col from W^T: lane holds n = nb2*16 + (w/2)*8 + lane/4,
// k = kstep*16 + (lane%4)*2 + (w%2)*8, packed as fp16 pair (k, k+1).
__global__ void k_prep(const float* __restrict__ W1, const float* __restrict__ W2) {
    int i = blockIdx.x * blockDim.x + threadIdx.x;
    if (i < 131072) {
        int h = i >> 15;
        int rem = i & 32767;
        int kstep = rem >> 11;
        int rem3 = rem & 2047;
        int nb2 = rem3 >> 7;
        int rem4 = rem3 & 127;
        int lane = rem4 >> 2;
        int w = rem4 & 3;
        int n = nb2 * 16 + ((w >> 1) << 3) + (lane >> 2);
        int k = (kstep << 4) + ((lane & 3) << 1) + ((w & 1) << 3);
        float f0 = W1[((h << 8) + k) * 256 + n];
        float f1 = W1[((h << 8) + k + 1) * 256 + n];
        g_b1pk[i] = pk(__float2half_rn(f0), __float2half_rn(f1));
    } else if (i < 131072 + 32768) {
        int j = i - 131072;
        int h = j >> 13;
        int rem = j & 8191;
        int kstep = rem >> 9;
        int rem3 = rem & 511;
        int nb2 = rem3 >> 7;
        int rem4 = rem3 & 127;
        int lane = rem4 >> 2;
        int w = rem4 & 3;
        int n = nb2 * 16 + ((w >> 1) << 3) + (lane >> 2);
        int k = (kstep << 4) + ((lane & 3) << 1) + ((w & 1) << 3);
        float f0 = W2[((h << 8) + k) * 64 + n];
        float f1 = W2[((h << 8) + k + 1) * 64 + n];
        g_b2pk[j] = pk(__float2half_rn(f0), __float2half_rn(f1));
    }
}

// ---------------- fused MLP: HMMA fp16 x2-product, M=64 tiles, 2 CTAs/SM ----------------
// SMEM: 2 comps x [kslab(4)][row(64)][64 fp16] 8KB slabs = 64KB total.
static constexpr uint32_t SM_COMP = 32768;
static constexpr uint32_t SM_TOT  = 65536;

__global__ __launch_bounds__(256, 2) void k_fused(const float* __restrict__ X,
                                                  const float* __restrict__ b1,
                                                  const float* __restrict__ b2) {
    extern __shared__ char smem[];
    const uint32_t sb = smem_u32(smem);
    const int tid  = threadIdx.x;
    const int lane = tid & 31;
    const int wid  = tid >> 5;
    const int h    = blockIdx.y;
    const int m0   = blockIdx.x * 64;

    const int quad = lane >> 3;
    const uint32_t rowoff = ((quad & 1) << 3) | (lane & 7);
    const uint32_t kboff  = (quad >> 1) << 4;

    // ---- stage X split (fp16 hi/lo) into SMEM: 64 rows x 256 cols ----
    {
        const int row = tid >> 2;                // 0..63
        const int kh  = (tid & 3) << 6;          // 0,64,128,192
        const bool rok = (m0 + row) < NN;
        const float* xr = X + (size_t)(m0 + row) * INDIM + kh;
        const uint32_t slab = (uint32_t)(kh >> 6) * 8192u;
#pragma unroll
        for (int c8 = 0; c8 < 8; c8++) {
            float4 v0, v1;
            if (rok) {
                v0 = *(const float4*)(xr + c8 * 8);
                v1 = *(const float4*)(xr + c8 * 8 + 4);
            } else {
                v0 = make_float4(0.f, 0.f, 0.f, 0.f);
                v1 = v0;
            }
            __half h0,l0,h1,l1,h2,l2,h3,l3,h4,l4,h5,l5,h6,l6,h7,l7;
            fsplit(v0.x, h0, l0); fsplit(v0.y, h1, l1);
            fsplit(v0.z, h2, l2); fsplit(v0.w, h3, l3);
            fsplit(v1.x, h4, l4); fsplit(v1.y, h5, l5);
            fsplit(v1.z, h6, l6); fsplit(v1.w, h7, l7);
            uint32_t off = slab + SWZ((uint32_t)((row << 7) | (c8 << 4)));
            *(uint4*)(smem + off)           = make_uint4(pk(h0,h1), pk(h2,h3), pk(h4,h5), pk(h6,h7));
            *(uint4*)(smem + SM_COMP + off) = make_uint4(pk(l0,l1), pk(l2,l3), pk(l4,l5), pk(l6,l7));
        }
    }
    __syncthreads();

    // ---- GEMM1: C1[64x256] = A(64x256) @ W1 (fp16), 2 products (Ahi,Alo) ----
    const int mi = wid >> 2, ni = wid & 3;       // warp tile: 32 rows x 64 cols
    float acc[2][8][4];
#pragma unroll
    for (int a = 0; a < 2; a++)
#pragma unroll
        for (int b = 0; b < 8; b++)
#pragma unroll
            for (int c = 0; c < 4; c++) acc[a][b][c] = 0.f;

    {
        const uint4* bp = (const uint4*)g_b1pk + (size_t)h * 8192 + lane;
#pragma unroll 2
        for (int ks = 0; ks < 16; ks++) {
            uint4 bh[4];
#pragma unroll
            for (int q = 0; q < 4; q++)
                bh[q] = bp[ks * 512 + (ni * 4 + q) * 32];
            const uint32_t kb = ((uint32_t)(ks & 3) << 5) | kboff;
            const uint32_t slab = (uint32_t)(ks >> 2) * 8192u;
            uint32_t a[2][4];
#pragma unroll
            for (int mf = 0; mf < 2; mf++)
                ldsm4(a[mf], sb + slab + SWZ((uint32_t)(((mi * 32 + mf * 16 + rowoff) << 7)) | kb));
#pragma unroll
            for (int mf = 0; mf < 2; mf++)
#pragma unroll
                for (int q = 0; q < 4; q++) {
                    mma16816(acc[mf][q * 2 + 0], a[mf], bh[q].x, bh[q].y);
                    mma16816(acc[mf][q * 2 + 1], a[mf], bh[q].z, bh[q].w);
                }
#pragma unroll
            for (int mf = 0; mf < 2; mf++)
                ldsm4(a[mf], sb + SM_COMP + slab + SWZ((uint32_t)(((mi * 32 + mf * 16 + rowoff) << 7)) | kb));
#pragma unroll
            for (int mf = 0; mf < 2; mf++)
#pragma unroll
                for (int q = 0; q < 4; q++) {
                    mma16816(acc[mf][q * 2 + 0], a[mf], bh[q].x, bh[q].y);
                    mma16816(acc[mf][q * 2 + 1], a[mf], bh[q].z, bh[q].w);
                }
        }
    }
    __syncthreads();   // all GEMM1 reads of A done

    // ---- epilogue1: bias + relu + fp16 split, write hidden back into A buffer ----
#pragma unroll
    for (int j = 0; j < 8; j++) {
        int n = ni * 64 + (j >> 1) * 16 + (j & 1) * 8 + ((lane & 3) << 1);
        float bv0 = __ldg(&b1[(h << 8) + n]);
        float bv1 = __ldg(&b1[(h << 8) + n + 1]);
        uint32_t kslab = (uint32_t)(n >> 6) * 8192u;
        uint32_t cb = (uint32_t)(n & 63) << 1;
#pragma unroll
        for (int mf = 0; mf < 2; mf++) {
#pragma unroll
            for (int rr = 0; rr < 2; rr++) {
                int row = mi * 32 + mf * 16 + (lane >> 2) + rr * 8;
                float v0 = acc[mf][j][rr * 2]     + bv0;
                float v1 = acc[mf][j][rr * 2 + 1] + bv1;
                v0 = v0 > 0.f ? v0 : 0.f;
                v1 = v1 > 0.f ? v1 : 0.f;
                __half h0, l0, h1, l1;
                fsplit(v0, h0, l0); fsplit(v1, h1, l1);
                uint32_t off = kslab + SWZ((uint32_t)((row << 7)) | cb);
                *(uint32_t*)(smem + off)           = pk(h0, h1);
                *(uint32_t*)(smem + SM_COMP + off) = pk(l0, l1);
            }
        }
    }
    __syncthreads();

    // ---- GEMM2: C2[64x64] = hidden(64x256) @ W2 (fp16), 2 products ----
    float c2[2][2][4];
#pragma unroll
    for (int a = 0; a < 2; a++)
#pragma unroll
        for (int b = 0; b < 2; b++)
#pragma unroll
            for (int c = 0; c < 4; c++) c2[a][b][c] = 0.f;

    {
        const uint4* bp = (const uint4*)g_b2pk + (size_t)h * 2048 + ni * 32 + lane;
#pragma unroll 4
        for (int ks = 0; ks < 16; ks++) {
            uint4 bh = bp[ks * 128];
            const uint32_t kb = ((uint32_t)(ks & 3) << 5) | kboff;
            const uint32_t slab = (uint32_t)(ks >> 2) * 8192u;
            uint32_t a[2][4];
#pragma unroll
            for (int mf = 0; mf < 2; mf++)
                ldsm4(a[mf], sb + slab + SWZ((uint32_t)(((mi * 32 + mf * 16 + rowoff) << 7)) | kb));
#pragma unroll
            for (int mf = 0; mf < 2; mf++) {
                mma16816(c2[mf][0], a[mf], bh.x, bh.y);
                mma16816(c2[mf][1], a[mf], bh.z, bh.w);
            }
#pragma unroll
            for (int mf = 0; mf < 2; mf++)
                ldsm4(a[mf], sb + SM_COMP + slab + SWZ((uint32_t)(((mi * 32 + mf * 16 + rowoff) << 7)) | kb));
#pragma unroll
            for (int mf = 0; mf < 2; mf++) {
                mma16816(c2[mf][0], a[mf], bh.x, bh.y);
                mma16816(c2[mf][1], a[mf], bh.z, bh.w);
            }
        }
    }

    // ---- final: bias + store feats (fp16) ----
#pragma unroll
    for (int j = 0; j < 2; j++) {
        int n = ni * 16 + j * 8 + ((lane & 3) << 1);
        float bv0 = __ldg(&b2[(h << 6) + n]);
        float bv1 = __ldg(&b2[(h << 6) + n + 1]);
#pragma unroll
        for (int mf = 0; mf < 2; mf++) {
#pragma unroll
            for (int rr = 0; rr < 2; rr++) {
                int row = m0 + mi * 32 + mf * 16 + (lane >> 2) + rr * 8;
                if (row < NN) {
                    float v0 = c2[mf][j][rr * 2]     + bv0;
                    float v1 = c2[mf][j][rr * 2 + 1] + bv1;
                    *(uint32_t*)(g_featsh + ((size_t)h * NN + row) * OUTD + n) =
                        pk(__float2half_rn(v0), __float2half_rn(v1));
                }
            }
        }
    }
}

// ---------------- per-node attention dot products (fp16 feats) ----------------
__global__ __launch_bounds__(256) void k_scores(const float* __restrict__ aw,
                                                const float* __restrict__ ab) {
    int lane = threadIdx.x & 31;
    int warp = threadIdx.x >> 5;
    int n = blockIdx.x * 8 + warp;
    int h = blockIdx.y;
    if (n >= NN) return;
    const __half2* f = (const __half2*)(g_featsh + ((size_t)h * NN + n) * OUTD) + lane;
    const float* w = aw + h * (2 * OUTD + 1);
    float2 fv = __half22float2(f[0]);
    float s1 = fv.x * w[2 * lane]      + fv.y * w[2 * lane + 1];
    float s2 = fv.x * w[64 + 2 * lane] + fv.y * w[65 + 2 * lane];
#pragma unroll
    for (int o = 16; o; o >>= 1) {
        s1 += __shfl_xor_sync(0xffffffffu, s1, o);
        s2 += __shfl_xor_sync(0xffffffffu, s2, o);
    }
    if (lane == 0) {
        g_ssrc[h * NN + n] = s1 + ab[h];
        g_sdst[h * NN + n] = s2;
    }
}

// ---------------- edge softmax-aggregation: warp per (node, head) ----------------
__global__ __launch_bounds__(256) void k_pool(float* __restrict__ out,
                                              const float* __restrict__ aw) {
    int lane = threadIdx.x & 31;
    int gw = blockIdx.x * 8 + (threadIdx.x >> 5);
    if (gw >= NH * NN) return;
    int n = gw >> 2;
    int h = gw & 3;

    int s = g_rowptr[n];
    int e = g_rowptr[n + 1];
    float base = g_ssrc[h * NN + n];
    float awe  = __ldg(&aw[h * (2 * OUTD + 1) + 2 * OUTD]);
    const float*   sd = g_sdst + (size_t)h * NN;
    const __half2* f2 = (const __half2*)(g_featsh + (size_t)h * NN * OUTD);

    float ax = 0.f, ay = 0.f, wsum = 0.f;
    for (int i = s; i < e; i++) {
        int d    = g_edst[i];
        float sc = base + sd[d] + g_eelem[i] * awe;
        float w  = __expf(sc);
        float2 f = __half22float2(f2[(size_t)d * 32 + lane]);
        ax = fmaf(w, f.x, ax);
        ay = fmaf(w, f.y, ay);
        wsum += w;
    }
    float2 o;
    o.x = ax / wsum;
    o.y = ay / wsum;
    *(float2*)(out + (size_t)n * (NH * OUTD) + h * OUTD + 2 * lane) = o;
}

// ---------------- launch ----------------
extern "C" void kernel_launch(void* const* d_in, const int* in_sizes, int n_in,
                              void* d_out, int out_size) {
    const float* x    = (const float*)d_in[0];
    const void*  idx  = d_in[1];
    const float* elem = (const float*)d_in[2];
    const float* W1   = (const float*)d_in[3];
    const float* b1   = (const float*)d_in[4];
    const float* W2   = (const float*)d_in[5];
    const float* b2   = (const float*)d_in[6];
    const float* aw   = (const float*)d_in[7];
    const float* ab   = (const float*)d_in[8];
    float* out = (float*)d_out;

    cudaFuncSetAttribute(k_fused, cudaFuncAttributeMaxDynamicSharedMemorySize, SM_TOT);

    // CSR build
    k_zero   <<<(NN + 255) / 256, 256>>>();
    k_hist   <<<(NE + 255) / 256, 256>>>(idx);
    k_scan   <<<1, 1024>>>();
    k_scatter<<<(NE + 255) / 256, 256>>>(idx, elem);

    // weight prep (fp16 fragment pack)
    k_prep<<<(131072 + 32768 + 255) / 256, 256>>>(W1, W2);

    // fused MLP (M=64 tiles, 2 CTAs/SM, 2-product fp16)
    dim3 gf((NN + 63) / 64, NH);
    k_fused<<<gf, 256, SM_TOT>>>(x, b1, b2);

    // attention dots + aggregation
    dim3 gs((NN + 7) / 8, NH);
    k_scores<<<gs, 256>>>(aw, ab);
    k_pool  <<<(NH * NN + 7) / 8, 256>>>(out, aw);
}

// round 10
// speedup vs baseline: 2.4969x; 1.1040x over previous
#include <cuda_runtime.h>
#include <cuda_fp16.h>
#include <cstdint>
#include <cstddef>

#define NN 50000
#define NE 800000
#define INDIM 256
#define HID 256
#define OUTD 64
#define NH 4

#define SWZ(o) ((o) ^ (((o) >> 3) & 0x70))

// ---------------- device scratch (static allocation only) ----------------
__device__ int   g_deg[NN];
__device__ int   g_cursor[NN];
__device__ int   g_rowptr[NN + 1];
__device__ int   g_edst[NE];
__device__ float g_eelem[NE];
__device__ __align__(16) __half g_featsh[(size_t)NH * NN * OUTD];  // [h][n][64] fp16
__device__ float g_ssrc[NH * NN];
__device__ float g_sdst[NH * NN];
// fragment-packed fp16 weights: [h][kstep][nb2][lane][w] uint32 (fp16x2)
__device__ __align__(16) uint32_t g_b1pk[4 * 16 * 16 * 32 * 4];  // 512KB
__device__ __align__(16) uint32_t g_b2pk[4 * 16 * 4 * 32 * 4];   // 128KB

// ---------------- helpers ----------------
__device__ __forceinline__ uint32_t smem_u32(const void* p) {
    uint32_t a;
    asm("{ .reg .u64 t; cvta.to.shared.u64 t, %1; cvt.u32.u64 %0, t; }" : "=r"(a) : "l"(p));
    return a;
}
__device__ __forceinline__ uint32_t pk(__half a, __half b) {
    __half2 t = __halves2half2(a, b);   // a -> low half
    return reinterpret_cast<uint32_t&>(t);
}
__device__ __forceinline__ uint32_t pkf(float a, float b) {
    __half2 t = __floats2half2_rn(a, b);
    return reinterpret_cast<uint32_t&>(t);
}
__device__ __forceinline__ void ldsm4(uint32_t* r, uint32_t addr) {
    asm volatile("ldmatrix.sync.aligned.m8n8.x4.shared.b16 {%0,%1,%2,%3}, [%4];"
                 : "=r"(r[0]), "=r"(r[1]), "=r"(r[2]), "=r"(r[3]) : "r"(addr));
}
__device__ __forceinline__ void mma16816(float* c, const uint32_t* a, uint32_t b0, uint32_t b1) {
    asm volatile("mma.sync.aligned.m16n8k16.row.col.f32.f16.f16.f32 "
                 "{%0,%1,%2,%3}, {%4,%5,%6,%7}, {%8,%9}, {%0,%1,%2,%3};"
                 : "+f"(c[0]), "+f"(c[1]), "+f"(c[2]), "+f"(c[3])
                 : "r"(a[0]), "r"(a[1]), "r"(a[2]), "r"(a[3]), "r"(b0), "r"(b1));
}

// ---------------- idx dtype sniff ----------------
__device__ __forceinline__ bool idx_is64(const int* p) {
    return (p[1] | p[3] | p[5] | p[7]) == 0;
}
__device__ __forceinline__ int load_src(const void* idx, int e, bool is64) {
    return is64 ? (int)((const long long*)idx)[e] : ((const int*)idx)[e];
}
__device__ __forceinline__ int load_dst(const void* idx, int e, bool is64) {
    return is64 ? (int)((const long long*)idx)[NE + e] : ((const int*)idx)[NE + e];
}

// ---------------- CSR build ----------------
__global__ void k_zero() {
    int i = blockIdx.x * blockDim.x + threadIdx.x;
    if (i < NN) { g_deg[i] = 0; g_cursor[i] = 0; }
}
__global__ void k_hist(const void* __restrict__ idx) {
    bool is64 = idx_is64((const int*)idx);
    int e = blockIdx.x * blockDim.x + threadIdx.x;
    if (e < NE) atomicAdd(&g_deg[load_src(idx, e, is64)], 1);
}
__global__ void k_scan() {
    __shared__ int sm[1024];
    const int CH = 49;
    int t = threadIdx.x;
    int base = t * CH, s = 0;
    for (int i = 0; i < CH; i++) { int g = base + i; if (g < NN) s += g_deg[g]; }
    sm[t] = s;
    __syncthreads();
    for (int off = 1; off < 1024; off <<= 1) {
        int v = (t >= off) ? sm[t - off] : 0;
        __syncthreads();
        sm[t] += v;
        __syncthreads();
    }
    int run = sm[t] - s;
    for (int i = 0; i < CH; i++) {
        int g = base + i;
        if (g <= NN) g_rowptr[g] = run;
        if (g < NN)  run += g_deg[g];
    }
}
__global__ void k_scatter(const void* __restrict__ idx, const float* __restrict__ elem) {
    bool is64 = idx_is64((const int*)idx);
    int e = blockIdx.x * blockDim.x + threadIdx.x;
    if (e < NE) {
        int s = load_src(idx, e, is64);
        int pos = g_rowptr[s] + atomicAdd(&g_cursor[s], 1);
        g_edst[pos]  = load_dst(idx, e, is64);
        g_eelem[pos] = elem[e];
    }
}

// ---------------- weight prep: transpose + fp16 + fragment packing ----------------
__global__ void k_prep(const float* __restrict__ W1, const float* __restrict__ W2) {
    int i = blockIdx.x * blockDim.x + threadIdx.x;
    if (i < 131072) {
        int h = i >> 15;
        int rem = i & 32767;
        int kstep = rem >> 11;
        int rem3 = rem & 2047;
        int nb2 = rem3 >> 7;
        int rem4 = rem3 & 127;
        int lane = rem4 >> 2;
        int w = rem4 & 3;
        int n = nb2 * 16 + ((w >> 1) << 3) + (lane >> 2);
        int k = (kstep << 4) + ((lane & 3) << 1) + ((w & 1) << 3);
        float f0 = W1[((h << 8) + k) * 256 + n];
        float f1 = W1[((h << 8) + k + 1) * 256 + n];
        g_b1pk[i] = pkf(f0, f1);
    } else if (i < 131072 + 32768) {
        int j = i - 131072;
        int h = j >> 13;
        int rem = j & 8191;
        int kstep = rem >> 9;
        int rem3 = rem & 511;
        int nb2 = rem3 >> 7;
        int rem4 = rem3 & 127;
        int lane = rem4 >> 2;
        int w = rem4 & 3;
        int n = nb2 * 16 + ((w >> 1) << 3) + (lane >> 2);
        int k = (kstep << 4) + ((lane & 3) << 1) + ((w & 1) << 3);
        float f0 = W2[((h << 8) + k) * 64 + n];
        float f1 = W2[((h << 8) + k + 1) * 64 + n];
        g_b2pk[j] = pkf(f0, f1);
    }
}

// ---------------- fused MLP: straight fp16 HMMA, M=64 tiles ----------------
// SMEM: [kslab(4)][row(64)][64 fp16] 8KB slabs = 32KB total.
static constexpr uint32_t SM_TOT = 32768;

__global__ __launch_bounds__(256, 2) void k_fused(const float* __restrict__ X,
                                                  const float* __restrict__ b1,
                                                  const float* __restrict__ b2) {
    extern __shared__ char smem[];
    const uint32_t sb = smem_u32(smem);
    const int tid  = threadIdx.x;
    const int lane = tid & 31;
    const int wid  = tid >> 5;
    const int h    = blockIdx.y;
    const int m0   = blockIdx.x * 64;

    const int quad = lane >> 3;
    const uint32_t rowoff = ((quad & 1) << 3) | (lane & 7);
    const uint32_t kboff  = (quad >> 1) << 4;

    // ---- stage X (fp16) into SMEM: 64 rows x 256 cols, 4 threads/row ----
    {
        const int row = tid >> 2;                // 0..63
        const int kh  = (tid & 3) << 6;          // 0,64,128,192
        const bool rok = (m0 + row) < NN;
        const float* xr = X + (size_t)(m0 + row) * INDIM + kh;
        const uint32_t slab = (uint32_t)(kh >> 6) * 8192u;
#pragma unroll
        for (int c8 = 0; c8 < 8; c8++) {
            float4 v0, v1;
            if (rok) {
                v0 = *(const float4*)(xr + c8 * 8);
                v1 = *(const float4*)(xr + c8 * 8 + 4);
            } else {
                v0 = make_float4(0.f, 0.f, 0.f, 0.f);
                v1 = v0;
            }
            uint32_t off = slab + SWZ((uint32_t)((row << 7) | (c8 << 4)));
            *(uint4*)(smem + off) =
                make_uint4(pkf(v0.x, v0.y), pkf(v0.z, v0.w), pkf(v1.x, v1.y), pkf(v1.z, v1.w));
        }
    }
    __syncthreads();

    // ---- GEMM1: C1[64x256] = A(64x256) @ W1 (fp16, single product) ----
    const int mi = wid >> 2, ni = wid & 3;       // warp tile: 32 rows x 64 cols
    float acc[2][8][4];
#pragma unroll
    for (int a = 0; a < 2; a++)
#pragma unroll
        for (int b = 0; b < 8; b++)
#pragma unroll
            for (int c = 0; c < 4; c++) acc[a][b][c] = 0.f;

    {
        const uint4* bp = (const uint4*)g_b1pk + (size_t)h * 8192 + lane;
#pragma unroll 4
        for (int ks = 0; ks < 16; ks++) {
            uint4 bh[4];
#pragma unroll
            for (int q = 0; q < 4; q++)
                bh[q] = bp[ks * 512 + (ni * 4 + q) * 32];
            const uint32_t kb = ((uint32_t)(ks & 3) << 5) | kboff;
            const uint32_t slab = (uint32_t)(ks >> 2) * 8192u;
            uint32_t a[2][4];
#pragma unroll
            for (int mf = 0; mf < 2; mf++)
                ldsm4(a[mf], sb + slab + SWZ((uint32_t)(((mi * 32 + mf * 16 + rowoff) << 7)) | kb));
#pragma unroll
            for (int mf = 0; mf < 2; mf++)
#pragma unroll
                for (int q = 0; q < 4; q++) {
                    mma16816(acc[mf][q * 2 + 0], a[mf], bh[q].x, bh[q].y);
                    mma16816(acc[mf][q * 2 + 1], a[mf], bh[q].z, bh[q].w);
                }
        }
    }
    __syncthreads();   // all GEMM1 reads of A done

    // ---- epilogue1: bias + relu + fp16, write hidden back into A buffer ----
#pragma unroll
    for (int j = 0; j < 8; j++) {
        int n = ni * 64 + (j >> 1) * 16 + (j & 1) * 8 + ((lane & 3) << 1);
        float bv0 = __ldg(&b1[(h << 8) + n]);
        float bv1 = __ldg(&b1[(h << 8) + n + 1]);
        uint32_t kslab = (uint32_t)(n >> 6) * 8192u;
        uint32_t cb = (uint32_t)(n & 63) << 1;
#pragma unroll
        for (int mf = 0; mf < 2; mf++) {
#pragma unroll
            for (int rr = 0; rr < 2; rr++) {
                int row = mi * 32 + mf * 16 + (lane >> 2) + rr * 8;
                float v0 = acc[mf][j][rr * 2]     + bv0;
                float v1 = acc[mf][j][rr * 2 + 1] + bv1;
                v0 = v0 > 0.f ? v0 : 0.f;
                v1 = v1 > 0.f ? v1 : 0.f;
                *(uint32_t*)(smem + kslab + SWZ((uint32_t)((row << 7)) | cb)) = pkf(v0, v1);
            }
        }
    }
    __syncthreads();

    // ---- GEMM2: C2[64x64] = hidden(64x256) @ W2 (fp16, single product) ----
    float c2[2][2][4];
#pragma unroll
    for (int a = 0; a < 2; a++)
#pragma unroll
        for (int b = 0; b < 2; b++)
#pragma unroll
            for (int c = 0; c < 4; c++) c2[a][b][c] = 0.f;

    {
        const uint4* bp = (const uint4*)g_b2pk + (size_t)h * 2048 + ni * 32 + lane;
#pragma unroll 4
        for (int ks = 0; ks < 16; ks++) {
            uint4 bh = bp[ks * 128];
            const uint32_t kb = ((uint32_t)(ks & 3) << 5) | kboff;
            const uint32_t slab = (uint32_t)(ks >> 2) * 8192u;
            uint32_t a[2][4];
#pragma unroll
            for (int mf = 0; mf < 2; mf++)
                ldsm4(a[mf], sb + slab + SWZ((uint32_t)(((mi * 32 + mf * 16 + rowoff) << 7)) | kb));
#pragma unroll
            for (int mf = 0; mf < 2; mf++) {
                mma16816(c2[mf][0], a[mf], bh.x, bh.y);
                mma16816(c2[mf][1], a[mf], bh.z, bh.w);
            }
        }
    }

    // ---- final: bias + store feats (fp16) ----
#pragma unroll
    for (int j = 0; j < 2; j++) {
        int n = ni * 16 + j * 8 + ((lane & 3) << 1);
        float bv0 = __ldg(&b2[(h << 6) + n]);
        float bv1 = __ldg(&b2[(h << 6) + n + 1]);
#pragma unroll
        for (int mf = 0; mf < 2; mf++) {
#pragma unroll
            for (int rr = 0; rr < 2; rr++) {
                int row = m0 + mi * 32 + mf * 16 + (lane >> 2) + rr * 8;
                if (row < NN) {
                    float v0 = c2[mf][j][rr * 2]     + bv0;
                    float v1 = c2[mf][j][rr * 2 + 1] + bv1;
                    *(uint32_t*)(g_featsh + ((size_t)h * NN + row) * OUTD + n) = pkf(v0, v1);
                }
            }
        }
    }
}

// ---------------- per-node attention dot products (fp16 feats) ----------------
__global__ __launch_bounds__(256) void k_scores(const float* __restrict__ aw,
                                                const float* __restrict__ ab) {
    int lane = threadIdx.x & 31;
    int warp = threadIdx.x >> 5;
    int n = blockIdx.x * 8 + warp;
    int h = blockIdx.y;
    if (n >= NN) return;
    const __half2* f = (const __half2*)(g_featsh + ((size_t)h * NN + n) * OUTD) + lane;
    const float* w = aw + h * (2 * OUTD + 1);
    float2 fv = __half22float2(f[0]);
    float s1 = fv.x * w[2 * lane]      + fv.y * w[2 * lane + 1];
    float s2 = fv.x * w[64 + 2 * lane] + fv.y * w[65 + 2 * lane];
#pragma unroll
    for (int o = 16; o; o >>= 1) {
        s1 += __shfl_xor_sync(0xffffffffu, s1, o);
        s2 += __shfl_xor_sync(0xffffffffu, s2, o);
    }
    if (lane == 0) {
        g_ssrc[h * NN + n] = s1 + ab[h];
        g_sdst[h * NN + n] = s2;
    }
}

// ---------------- edge softmax-aggregation: warp per (node, head) ----------------
__global__ __launch_bounds__(256) void k_pool(float* __restrict__ out,
                                              const float* __restrict__ aw) {
    int lane = threadIdx.x & 31;
    int gw = blockIdx.x * 8 + (threadIdx.x >> 5);
    if (gw >= NH * NN) return;
    int n = gw >> 2;
    int h = gw & 3;

    int s = g_rowptr[n];
    int e = g_rowptr[n + 1];
    float base = g_ssrc[h * NN + n];
    float awe  = __ldg(&aw[h * (2 * OUTD + 1) + 2 * OUTD]);
    const float*   sd = g_sdst + (size_t)h * NN;
    const __half2* f2 = (const __half2*)(g_featsh + (size_t)h * NN * OUTD);

    float ax = 0.f, ay = 0.f, wsum = 0.f;
    for (int i = s; i < e; i++) {
        int d    = g_edst[i];
        float sc = base + sd[d] + g_eelem[i] * awe;
        float w  = __expf(sc);
        float2 f = __half22float2(f2[(size_t)d * 32 + lane]);
        ax = fmaf(w, f.x, ax);
        ay = fmaf(w, f.y, ay);
        wsum += w;
    }
    float2 o;
    o.x = ax / wsum;
    o.y = ay / wsum;
    *(float2*)(out + (size_t)n * (NH * OUTD) + h * OUTD + 2 * lane) = o;
}

// ---------------- launch ----------------
extern "C" void kernel_launch(void* const* d_in, const int* in_sizes, int n_in,
                              void* d_out, int out_size) {
    const float* x    = (const float*)d_in[0];
    const void*  idx  = d_in[1];
    const float* elem = (const float*)d_in[2];
    const float* W1   = (const float*)d_in[3];
    const float* b1   = (const float*)d_in[4];
    const float* W2   = (const float*)d_in[5];
    const float* b2   = (const float*)d_in[6];
    const float* aw   = (const float*)d_in[7];
    const float* ab   = (const float*)d_in[8];
    float* out = (float*)d_out;

    cudaFuncSetAttribute(k_fused, cudaFuncAttributeMaxDynamicSharedMemorySize, SM_TOT);

    // CSR build
    k_zero   <<<(NN + 255) / 256, 256>>>();
    k_hist   <<<(NE + 255) / 256, 256>>>(idx);
    k_scan   <<<1, 1024>>>();
    k_scatter<<<(NE + 255) / 256, 256>>>(idx, elem);

    // weight prep (fp16 fragment pack)
    k_prep<<<(131072 + 32768 + 255) / 256, 256>>>(W1, W2);

    // fused MLP (M=64 tiles, single-product fp16)
    dim3 gf((NN + 63) / 64, NH);
    k_fused<<<gf, 256, SM_TOT>>>(x, b1, b2);

    // attention dots + aggregation
    dim3 gs((NN + 7) / 8, NH);
    k_scores<<<gs, 256>>>(aw, ab);
    k_pool  <<<(NH * NN + 7) / 8, 256>>>(out, aw);
}

// round 11
// speedup vs baseline: 3.1410x; 1.2579x over previous
#include <cuda_runtime.h>
#include <cuda_fp16.h>
#include <cstdint>
#include <cstddef>

#define NN 50000
#define NE 800000
#define INDIM 256
#define HID 256
#define OUTD 64
#define NH 4

#define SWZ(o) ((o) ^ (((o) >> 3) & 0x70))

// ---------------- device scratch (static allocation only) ----------------
__device__ int   g_deg[NN];
__device__ int   g_cursor[NN];
__device__ int   g_rowptr[NN + 1];
__device__ int   g_edst[NE];
__device__ float g_eelem[NE];
__device__ __align__(16) __half g_featsh[(size_t)NH * NN * OUTD];  // [h][n][64] fp16
__device__ float g_ssrc[NH * NN];
__device__ float g_sdst[NH * NN];
// fragment-packed fp16 weights: [h][kstep][nb2][lane][w] uint32 (fp16x2)
__device__ __align__(16) uint32_t g_b1pk[4 * 16 * 16 * 32 * 4];  // 512KB
__device__ __align__(16) uint32_t g_b2pk[4 * 16 * 4 * 32 * 4];   // 128KB

// ---------------- helpers ----------------
__device__ __forceinline__ uint32_t smem_u32(const void* p) {
    uint32_t a;
    asm("{ .reg .u64 t; cvta.to.shared.u64 t, %1; cvt.u32.u64 %0, t; }" : "=r"(a) : "l"(p));
    return a;
}
__device__ __forceinline__ uint32_t pkf(float a, float b) {
    __half2 t = __floats2half2_rn(a, b);
    return reinterpret_cast<uint32_t&>(t);
}
__device__ __forceinline__ void ldsm4(uint32_t* r, uint32_t addr) {
    asm volatile("ldmatrix.sync.aligned.m8n8.x4.shared.b16 {%0,%1,%2,%3}, [%4];"
                 : "=r"(r[0]), "=r"(r[1]), "=r"(r[2]), "=r"(r[3]) : "r"(addr));
}
__device__ __forceinline__ void mma16816(float* c, const uint32_t* a, uint32_t b0, uint32_t b1) {
    asm volatile("mma.sync.aligned.m16n8k16.row.col.f32.f16.f16.f32 "
                 "{%0,%1,%2,%3}, {%4,%5,%6,%7}, {%8,%9}, {%0,%1,%2,%3};"
                 : "+f"(c[0]), "+f"(c[1]), "+f"(c[2]), "+f"(c[3])
                 : "r"(a[0]), "r"(a[1]), "r"(a[2]), "r"(a[3]), "r"(b0), "r"(b1));
}

// ---------------- idx dtype sniff ----------------
__device__ __forceinline__ bool idx_is64(const int* p) {
    return (p[1] | p[3] | p[5] | p[7]) == 0;
}
__device__ __forceinline__ int load_src(const void* idx, int e, bool is64) {
    return is64 ? (int)((const long long*)idx)[e] : ((const int*)idx)[e];
}
__device__ __forceinline__ int load_dst(const void* idx, int e, bool is64) {
    return is64 ? (int)((const long long*)idx)[NE + e] : ((const int*)idx)[NE + e];
}

// ---------------- CSR: zero ----------------
__global__ void k_zero() {
    int i = blockIdx.x * blockDim.x + threadIdx.x;
    if (i < NN) { g_deg[i] = 0; g_cursor[i] = 0; }
}

// ---------------- merged: histogram (blocks 0..3124) + weight prep (3125..3764) --------
#define HIST_BLOCKS 3125
__global__ void k_histprep(const void* __restrict__ idx,
                           const float* __restrict__ W1,
                           const float* __restrict__ W2) {
    int b = blockIdx.x;
    int t = threadIdx.x;
    if (b < HIST_BLOCKS) {
        bool is64 = idx_is64((const int*)idx);
        int e = b * 256 + t;
        if (e < NE) atomicAdd(&g_deg[load_src(idx, e, is64)], 1);
        return;
    }
    int i = (b - HIST_BLOCKS) * 256 + t;
    if (i < 131072) {
        int h = i >> 15;
        int rem = i & 32767;
        int kstep = rem >> 11;
        int rem3 = rem & 2047;
        int nb2 = rem3 >> 7;
        int rem4 = rem3 & 127;
        int lane = rem4 >> 2;
        int w = rem4 & 3;
        int n = nb2 * 16 + ((w >> 1) << 3) + (lane >> 2);
        int k = (kstep << 4) + ((lane & 3) << 1) + ((w & 1) << 3);
        float f0 = W1[((h << 8) + k) * 256 + n];
        float f1 = W1[((h << 8) + k + 1) * 256 + n];
        g_b1pk[i] = pkf(f0, f1);
    } else if (i < 131072 + 32768) {
        int j = i - 131072;
        int h = j >> 13;
        int rem = j & 8191;
        int kstep = rem >> 9;
        int rem3 = rem & 511;
        int nb2 = rem3 >> 7;
        int rem4 = rem3 & 127;
        int lane = rem4 >> 2;
        int w = rem4 & 3;
        int n = nb2 * 16 + ((w >> 1) << 3) + (lane >> 2);
        int k = (kstep << 4) + ((lane & 3) << 1) + ((w & 1) << 3);
        float f0 = W2[((h << 8) + k) * 64 + n];
        float f1 = W2[((h << 8) + k + 1) * 64 + n];
        g_b2pk[j] = pkf(f0, f1);
    }
}

// ---------------- CSR: scan ----------------
__global__ void k_scan() {
    __shared__ int sm[1024];
    const int CH = 49;
    int t = threadIdx.x;
    int base = t * CH, s = 0;
    for (int i = 0; i < CH; i++) { int g = base + i; if (g < NN) s += g_deg[g]; }
    sm[t] = s;
    __syncthreads();
    for (int off = 1; off < 1024; off <<= 1) {
        int v = (t >= off) ? sm[t - off] : 0;
        __syncthreads();
        sm[t] += v;
        __syncthreads();
    }
    int run = sm[t] - s;
    for (int i = 0; i < CH; i++) {
        int g = base + i;
        if (g <= NN) g_rowptr[g] = run;
        if (g < NN)  run += g_deg[g];
    }
}

// ---------------- fused MLP (y==0) + CSR scatter (y==1) ----------------
// SMEM: X fp16 at 0 (32KB: 4 kslabs x 8KB), hidden/feats scratch at 32KB (32KB).
static constexpr uint32_t SM_H   = 32768;
static constexpr uint32_t SM_TOT = 65536;
#define FGRID 782

__global__ __launch_bounds__(256, 2) void k_fused(const float* __restrict__ X,
                                                  const float* __restrict__ b1,
                                                  const float* __restrict__ b2,
                                                  const float* __restrict__ aw,
                                                  const float* __restrict__ ab,
                                                  const void* __restrict__ idx,
                                                  const float* __restrict__ elem) {
    // ----- scatter blocks -----
    if (blockIdx.y == 1) {
        bool is64 = idx_is64((const int*)idx);
        int gt = blockIdx.x * 256 + threadIdx.x;
        for (int e = gt; e < NE; e += FGRID * 256) {
            int s = load_src(idx, e, is64);
            int pos = g_rowptr[s] + atomicAdd(&g_cursor[s], 1);
            g_edst[pos]  = load_dst(idx, e, is64);
            g_eelem[pos] = elem[e];
        }
        return;
    }

    extern __shared__ char smem[];
    const uint32_t sb = smem_u32(smem);
    const int tid  = threadIdx.x;
    const int lane = tid & 31;
    const int wid  = tid >> 5;
    const int m0   = blockIdx.x * 64;

    const int quad = lane >> 3;
    const uint32_t rowoff = ((quad & 1) << 3) | (lane & 7);
    const uint32_t kboff  = (quad >> 1) << 4;

    // ---- stage X (fp16) into SMEM once: 64 rows x 256 cols ----
    {
        const int row = tid >> 2;                // 0..63
        const int kh  = (tid & 3) << 6;          // 0,64,128,192
        const bool rok = (m0 + row) < NN;
        const float* xr = X + (size_t)(m0 + row) * INDIM + kh;
        const uint32_t slab = (uint32_t)(kh >> 6) * 8192u;
#pragma unroll
        for (int c8 = 0; c8 < 8; c8++) {
            float4 v0, v1;
            if (rok) {
                v0 = *(const float4*)(xr + c8 * 8);
                v1 = *(const float4*)(xr + c8 * 8 + 4);
            } else {
                v0 = make_float4(0.f, 0.f, 0.f, 0.f);
                v1 = v0;
            }
            uint32_t off = slab + SWZ((uint32_t)((row << 7) | (c8 << 4)));
            *(uint4*)(smem + off) =
                make_uint4(pkf(v0.x, v0.y), pkf(v0.z, v0.w), pkf(v1.x, v1.y), pkf(v1.z, v1.w));
        }
    }
    __syncthreads();

    const int mi = wid >> 2, ni = wid & 3;       // warp tile: 32 rows x 64 cols

    for (int h = 0; h < NH; h++) {
        // ---- GEMM1: C1[64x256] = X @ W1[h] (fp16) ----
        float acc[2][8][4];
#pragma unroll
        for (int a = 0; a < 2; a++)
#pragma unroll
            for (int b = 0; b < 8; b++)
#pragma unroll
                for (int c = 0; c < 4; c++) acc[a][b][c] = 0.f;
        {
            const uint4* bp = (const uint4*)g_b1pk + (size_t)h * 8192 + lane;
#pragma unroll 4
            for (int ks = 0; ks < 16; ks++) {
                uint4 bh[4];
#pragma unroll
                for (int q = 0; q < 4; q++)
                    bh[q] = bp[ks * 512 + (ni * 4 + q) * 32];
                const uint32_t kb = ((uint32_t)(ks & 3) << 5) | kboff;
                const uint32_t slab = (uint32_t)(ks >> 2) * 8192u;
                uint32_t a[2][4];
#pragma unroll
                for (int mf = 0; mf < 2; mf++)
                    ldsm4(a[mf], sb + slab + SWZ((uint32_t)(((mi * 32 + mf * 16 + rowoff) << 7)) | kb));
#pragma unroll
                for (int mf = 0; mf < 2; mf++)
#pragma unroll
                    for (int q = 0; q < 4; q++) {
                        mma16816(acc[mf][q * 2 + 0], a[mf], bh[q].x, bh[q].y);
                        mma16816(acc[mf][q * 2 + 1], a[mf], bh[q].z, bh[q].w);
                    }
            }
        }
        __syncthreads();   // prior-head dot reads of SM_H done; all warps here

        // ---- epilogue1: bias + relu + fp16 -> hidden buffer ----
#pragma unroll
        for (int j = 0; j < 8; j++) {
            int n = ni * 64 + (j >> 1) * 16 + (j & 1) * 8 + ((lane & 3) << 1);
            float bv0 = __ldg(&b1[(h << 8) + n]);
            float bv1 = __ldg(&b1[(h << 8) + n + 1]);
            uint32_t kslab = SM_H + (uint32_t)(n >> 6) * 8192u;
            uint32_t cb = (uint32_t)(n & 63) << 1;
#pragma unroll
            for (int mf = 0; mf < 2; mf++) {
#pragma unroll
                for (int rr = 0; rr < 2; rr++) {
                    int row = mi * 32 + mf * 16 + (lane >> 2) + rr * 8;
                    float v0 = acc[mf][j][rr * 2]     + bv0;
                    float v1 = acc[mf][j][rr * 2 + 1] + bv1;
                    v0 = v0 > 0.f ? v0 : 0.f;
                    v1 = v1 > 0.f ? v1 : 0.f;
                    *(uint32_t*)(smem + kslab + SWZ((uint32_t)((row << 7)) | cb)) = pkf(v0, v1);
                }
            }
        }
        __syncthreads();

        // ---- GEMM2: C2[64x64] = hidden @ W2[h] (fp16) ----
        float c2[2][2][4];
#pragma unroll
        for (int a = 0; a < 2; a++)
#pragma unroll
            for (int b = 0; b < 2; b++)
#pragma unroll
                for (int c = 0; c < 4; c++) c2[a][b][c] = 0.f;
        {
            const uint4* bp = (const uint4*)g_b2pk + (size_t)h * 2048 + ni * 32 + lane;
#pragma unroll 4
            for (int ks = 0; ks < 16; ks++) {
                uint4 bh = bp[ks * 128];
                const uint32_t kb = ((uint32_t)(ks & 3) << 5) | kboff;
                const uint32_t slab = SM_H + (uint32_t)(ks >> 2) * 8192u;
                uint32_t a[2][4];
#pragma unroll
                for (int mf = 0; mf < 2; mf++)
                    ldsm4(a[mf], sb + slab + SWZ((uint32_t)(((mi * 32 + mf * 16 + rowoff) << 7)) | kb));
#pragma unroll
                for (int mf = 0; mf < 2; mf++) {
                    mma16816(c2[mf][0], a[mf], bh.x, bh.y);
                    mma16816(c2[mf][1], a[mf], bh.z, bh.w);
                }
            }
        }
        __syncthreads();   // all GEMM2 reads of hidden done before f32 overwrite

        // ---- epilogue2: bias; store feats (fp16 global) + fp32 copy in SMEM ----
        float* fs = (float*)(smem + SM_H);       // [row][65] fp32
#pragma unroll
        for (int j = 0; j < 2; j++) {
            int n = ni * 16 + j * 8 + ((lane & 3) << 1);
            float bv0 = __ldg(&b2[(h << 6) + n]);
            float bv1 = __ldg(&b2[(h << 6) + n + 1]);
#pragma unroll
            for (int mf = 0; mf < 2; mf++) {
#pragma unroll
                for (int rr = 0; rr < 2; rr++) {
                    int row = mi * 32 + mf * 16 + (lane >> 2) + rr * 8;
                    float v0 = c2[mf][j][rr * 2]     + bv0;
                    float v1 = c2[mf][j][rr * 2 + 1] + bv1;
                    fs[row * 65 + n]     = v0;
                    fs[row * 65 + n + 1] = v1;
                    int gr = m0 + row;
                    if (gr < NN)
                        *(uint32_t*)(g_featsh + ((size_t)h * NN + gr) * OUTD + n) = pkf(v0, v1);
                }
            }
        }
        __syncthreads();

        // ---- attention dots from fp32 feats (warps 0-1, lane = row) ----
        if (wid < 2) {
            int row = wid * 32 + lane;
            int m = m0 + row;
            if (m < NN) {
                const float* fr = fs + row * 65;
                const float* awh = aw + h * (2 * OUTD + 1);
                float s1 = 0.f, s2 = 0.f;
#pragma unroll 8
                for (int c = 0; c < 64; c++) {
                    float v = fr[c];
                    s1 = fmaf(v, __ldg(&awh[c]), s1);
                    s2 = fmaf(v, __ldg(&awh[64 + c]), s2);
                }
                g_ssrc[h * NN + m] = s1 + __ldg(&ab[h]);
                g_sdst[h * NN + m] = s2;
            }
        }
    }
}

// ---------------- edge softmax-aggregation: warp per (node, head), unroll-4 ----------------
__global__ __launch_bounds__(256) void k_pool(float* __restrict__ out,
                                              const float* __restrict__ aw) {
    int lane = threadIdx.x & 31;
    int gw = blockIdx.x * 8 + (threadIdx.x >> 5);
    if (gw >= NH * NN) return;
    int n = gw >> 2;
    int h = gw & 3;

    int s = g_rowptr[n];
    int e = g_rowptr[n + 1];
    float base = g_ssrc[h * NN + n];
    float awe  = __ldg(&aw[h * (2 * OUTD + 1) + 2 * OUTD]);
    const float*   sd = g_sdst + (size_t)h * NN;
    const __half2* fp = (const __half2*)(g_featsh + (size_t)h * NN * OUTD);

    float ax = 0.f, ay = 0.f, ws = 0.f;
    int i = s;
    for (; i + 4 <= e; i += 4) {
        int d0 = g_edst[i], d1 = g_edst[i + 1], d2 = g_edst[i + 2], d3 = g_edst[i + 3];
        float el0 = g_eelem[i], el1 = g_eelem[i + 1], el2 = g_eelem[i + 2], el3 = g_eelem[i + 3];
        float t0 = sd[d0], t1 = sd[d1], t2 = sd[d2], t3 = sd[d3];
        __half2 q0 = fp[(size_t)d0 * 32 + lane];
        __half2 q1 = fp[(size_t)d1 * 32 + lane];
        __half2 q2 = fp[(size_t)d2 * 32 + lane];
        __half2 q3 = fp[(size_t)d3 * 32 + lane];
        float w0 = __expf(base + t0 + el0 * awe);
        float w1 = __expf(base + t1 + el1 * awe);
        float w2 = __expf(base + t2 + el2 * awe);
        float w3 = __expf(base + t3 + el3 * awe);
        float2 f0 = __half22float2(q0), f1 = __half22float2(q1);
        float2 f2 = __half22float2(q2), f3 = __half22float2(q3);
        ax = fmaf(w0, f0.x, ax); ay = fmaf(w0, f0.y, ay);
        ax = fmaf(w1, f1.x, ax); ay = fmaf(w1, f1.y, ay);
        ax = fmaf(w2, f2.x, ax); ay = fmaf(w2, f2.y, ay);
        ax = fmaf(w3, f3.x, ax); ay = fmaf(w3, f3.y, ay);
        ws += (w0 + w1) + (w2 + w3);
    }
    for (; i < e; i++) {
        int d    = g_edst[i];
        float w  = __expf(base + sd[d] + g_eelem[i] * awe);
        float2 f = __half22float2(fp[(size_t)d * 32 + lane]);
        ax = fmaf(w, f.x, ax);
        ay = fmaf(w, f.y, ay);
        ws += w;
    }
    float2 o;
    o.x = ax / ws;
    o.y = ay / ws;
    *(float2*)(out + (size_t)n * (NH * OUTD) + h * OUTD + 2 * lane) = o;
}

// ---------------- launch ----------------
extern "C" void kernel_launch(void* const* d_in, const int* in_sizes, int n_in,
                              void* d_out, int out_size) {
    const float* x    = (const float*)d_in[0];
    const void*  idx  = d_in[1];
    const float* elem = (const float*)d_in[2];
    const float* W1   = (const float*)d_in[3];
    const float* b1   = (const float*)d_in[4];
    const float* W2   = (const float*)d_in[5];
    const float* b2   = (const float*)d_in[6];
    const float* aw   = (const float*)d_in[7];
    const float* ab   = (const float*)d_in[8];
    float* out = (float*)d_out;

    cudaFuncSetAttribute(k_fused, cudaFuncAttributeMaxDynamicSharedMemorySize, SM_TOT);

    k_zero<<<(NN + 255) / 256, 256>>>();
    k_histprep<<<HIST_BLOCKS + (131072 + 32768 + 255) / 256, 256>>>(idx, W1, W2);
    k_scan<<<1, 1024>>>();

    // fused MLP (y==0, head loop) + CSR scatter (y==1)
    dim3 gf(FGRID, 2);
    k_fused<<<gf, 256, SM_TOT>>>(x, b1, b2, aw, ab, idx, elem);

    // aggregation
    k_pool<<<(NH * NN + 7) / 8, 256>>>(out, aw);
}

// round 12
// speedup vs baseline: 3.1926x; 1.0164x over previous
#include <cuda_runtime.h>
#include <cuda_fp16.h>
#include <cstdint>
#include <cstddef>

#define NN 50000
#define NE 800000
#define INDIM 256
#define HID 256
#define OUTD 64
#define NH 4

#define SWZ(o) ((o) ^ (((o) >> 3) & 0x70))

// ---------------- device scratch (static allocation only) ----------------
__device__ int   g_deg[NN];
__device__ int   g_cursor[NN];
__device__ int   g_rowptr[NN + 1];
__device__ int   g_edst[NE];
__device__ float g_eelem[NE];
__device__ __align__(16) __half g_featsh[(size_t)NN * NH * OUTD]; // [n][h][64] fp16
__device__ __align__(16) float g_ssrc[NN * NH];                   // [n][h]
__device__ __align__(16) float g_sdst[NN * NH];                   // [n][h]
// fragment-packed fp16 weights: [h][kstep][nb2][lane][w] uint32 (fp16x2)
__device__ __align__(16) uint32_t g_b1pk[4 * 16 * 16 * 32 * 4];  // 512KB
__device__ __align__(16) uint32_t g_b2pk[4 * 16 * 4 * 32 * 4];   // 128KB

// ---------------- helpers ----------------
__device__ __forceinline__ uint32_t smem_u32(const void* p) {
    uint32_t a;
    asm("{ .reg .u64 t; cvta.to.shared.u64 t, %1; cvt.u32.u64 %0, t; }" : "=r"(a) : "l"(p));
    return a;
}
__device__ __forceinline__ uint32_t pkf(float a, float b) {
    __half2 t = __floats2half2_rn(a, b);
    return reinterpret_cast<uint32_t&>(t);
}
__device__ __forceinline__ void ldsm4(uint32_t* r, uint32_t addr) {
    asm volatile("ldmatrix.sync.aligned.m8n8.x4.shared.b16 {%0,%1,%2,%3}, [%4];"
                 : "=r"(r[0]), "=r"(r[1]), "=r"(r[2]), "=r"(r[3]) : "r"(addr));
}
__device__ __forceinline__ void mma16816(float* c, const uint32_t* a, uint32_t b0, uint32_t b1) {
    asm volatile("mma.sync.aligned.m16n8k16.row.col.f32.f16.f16.f32 "
                 "{%0,%1,%2,%3}, {%4,%5,%6,%7}, {%8,%9}, {%0,%1,%2,%3};"
                 : "+f"(c[0]), "+f"(c[1]), "+f"(c[2]), "+f"(c[3])
                 : "r"(a[0]), "r"(a[1]), "r"(a[2]), "r"(a[3]), "r"(b0), "r"(b1));
}

// ---------------- idx dtype sniff ----------------
__device__ __forceinline__ bool idx_is64(const int* p) {
    return (p[1] | p[3] | p[5] | p[7]) == 0;
}
__device__ __forceinline__ int load_src(const void* idx, int e, bool is64) {
    return is64 ? (int)((const long long*)idx)[e] : ((const int*)idx)[e];
}
__device__ __forceinline__ int load_dst(const void* idx, int e, bool is64) {
    return is64 ? (int)((const long long*)idx)[NE + e] : ((const int*)idx)[NE + e];
}

// ---------------- CSR: zero ----------------
__global__ void k_zero() {
    int i = blockIdx.x * blockDim.x + threadIdx.x;
    if (i < NN) { g_deg[i] = 0; g_cursor[i] = 0; }
}

// ---------------- merged: histogram + weight prep ----------------
#define HIST_BLOCKS 3125
__global__ void k_histprep(const void* __restrict__ idx,
                           const float* __restrict__ W1,
                           const float* __restrict__ W2) {
    int b = blockIdx.x;
    int t = threadIdx.x;
    if (b < HIST_BLOCKS) {
        bool is64 = idx_is64((const int*)idx);
        int e = b * 256 + t;
        if (e < NE) atomicAdd(&g_deg[load_src(idx, e, is64)], 1);
        return;
    }
    int i = (b - HIST_BLOCKS) * 256 + t;
    if (i < 131072) {
        int h = i >> 15;
        int rem = i & 32767;
        int kstep = rem >> 11;
        int rem3 = rem & 2047;
        int nb2 = rem3 >> 7;
        int rem4 = rem3 & 127;
        int lane = rem4 >> 2;
        int w = rem4 & 3;
        int n = nb2 * 16 + ((w >> 1) << 3) + (lane >> 2);
        int k = (kstep << 4) + ((lane & 3) << 1) + ((w & 1) << 3);
        float f0 = W1[((h << 8) + k) * 256 + n];
        float f1 = W1[((h << 8) + k + 1) * 256 + n];
        g_b1pk[i] = pkf(f0, f1);
    } else if (i < 131072 + 32768) {
        int j = i - 131072;
        int h = j >> 13;
        int rem = j & 8191;
        int kstep = rem >> 9;
        int rem3 = rem & 511;
        int nb2 = rem3 >> 7;
        int rem4 = rem3 & 127;
        int lane = rem4 >> 2;
        int w = rem4 & 3;
        int n = nb2 * 16 + ((w >> 1) << 3) + (lane >> 2);
        int k = (kstep << 4) + ((lane & 3) << 1) + ((w & 1) << 3);
        float f0 = W2[((h << 8) + k) * 64 + n];
        float f1 = W2[((h << 8) + k + 1) * 64 + n];
        g_b2pk[j] = pkf(f0, f1);
    }
}

// ---------------- CSR: scan ----------------
__global__ void k_scan() {
    __shared__ int sm[1024];
    const int CH = 49;
    int t = threadIdx.x;
    int base = t * CH, s = 0;
    for (int i = 0; i < CH; i++) { int g = base + i; if (g < NN) s += g_deg[g]; }
    sm[t] = s;
    __syncthreads();
    for (int off = 1; off < 1024; off <<= 1) {
        int v = (t >= off) ? sm[t - off] : 0;
        __syncthreads();
        sm[t] += v;
        __syncthreads();
    }
    int run = sm[t] - s;
    for (int i = 0; i < CH; i++) {
        int g = base + i;
        if (g <= NN) g_rowptr[g] = run;
        if (g < NN)  run += g_deg[g];
    }
}

// ---------------- fused MLP (y==0) + CSR scatter (y==1) ----------------
// SMEM: X fp16 at 0 (32KB: 4 kslabs x 8KB), hidden/feats scratch at 32KB (32KB).
static constexpr uint32_t SM_H   = 32768;
static constexpr uint32_t SM_TOT = 65536;
#define FGRID 782

__global__ __launch_bounds__(256, 3) void k_fused(const float* __restrict__ X,
                                                  const float* __restrict__ b1,
                                                  const float* __restrict__ b2,
                                                  const float* __restrict__ aw,
                                                  const float* __restrict__ ab,
                                                  const void* __restrict__ idx,
                                                  const float* __restrict__ elem) {
    // ----- scatter blocks -----
    if (blockIdx.y == 1) {
        bool is64 = idx_is64((const int*)idx);
        int gt = blockIdx.x * 256 + threadIdx.x;
        for (int e = gt; e < NE; e += FGRID * 256) {
            int s = load_src(idx, e, is64);
            int pos = g_rowptr[s] + atomicAdd(&g_cursor[s], 1);
            g_edst[pos]  = load_dst(idx, e, is64);
            g_eelem[pos] = elem[e];
        }
        return;
    }

    extern __shared__ char smem[];
    const uint32_t sb = smem_u32(smem);
    const int tid  = threadIdx.x;
    const int lane = tid & 31;
    const int wid  = tid >> 5;
    const int m0   = blockIdx.x * 64;

    const int quad = lane >> 3;
    const uint32_t rowoff = ((quad & 1) << 3) | (lane & 7);
    const uint32_t kboff  = (quad >> 1) << 4;

    // ---- stage X (fp16) into SMEM once: 64 rows x 256 cols ----
    {
        const int row = tid >> 2;                // 0..63
        const int kh  = (tid & 3) << 6;          // 0,64,128,192
        const bool rok = (m0 + row) < NN;
        const float* xr = X + (size_t)(m0 + row) * INDIM + kh;
        const uint32_t slab = (uint32_t)(kh >> 6) * 8192u;
#pragma unroll
        for (int c8 = 0; c8 < 8; c8++) {
            float4 v0, v1;
            if (rok) {
                v0 = *(const float4*)(xr + c8 * 8);
                v1 = *(const float4*)(xr + c8 * 8 + 4);
            } else {
                v0 = make_float4(0.f, 0.f, 0.f, 0.f);
                v1 = v0;
            }
            uint32_t off = slab + SWZ((uint32_t)((row << 7) | (c8 << 4)));
            *(uint4*)(smem + off) =
                make_uint4(pkf(v0.x, v0.y), pkf(v0.z, v0.w), pkf(v1.x, v1.y), pkf(v1.z, v1.w));
        }
    }
    __syncthreads();

    const int mi = wid >> 2, ni = wid & 3;

    for (int h = 0; h < NH; h++) {
        // ---- GEMM1 in two 128-col halves (acc 32 regs) ----
#pragma unroll 1
        for (int nh = 0; nh < 2; nh++) {
            float acc[2][4][4];
#pragma unroll
            for (int a = 0; a < 2; a++)
#pragma unroll
                for (int b = 0; b < 4; b++)
#pragma unroll
                    for (int c = 0; c < 4; c++) acc[a][b][c] = 0.f;

            const int nbase = nh * 8 + ni * 2;   // nb2 (16-col group) index
            const uint4* bp = (const uint4*)g_b1pk + (size_t)h * 8192 + lane;
#pragma unroll 4
            for (int ks = 0; ks < 16; ks++) {
                uint4 b0 = bp[ks * 512 + nbase * 32];
                uint4 b1v = bp[ks * 512 + (nbase + 1) * 32];
                const uint32_t kb = ((uint32_t)(ks & 3) << 5) | kboff;
                const uint32_t slab = (uint32_t)(ks >> 2) * 8192u;
                uint32_t a[2][4];
#pragma unroll
                for (int mf = 0; mf < 2; mf++)
                    ldsm4(a[mf], sb + slab + SWZ((uint32_t)(((mi * 32 + mf * 16 + rowoff) << 7)) | kb));
#pragma unroll
                for (int mf = 0; mf < 2; mf++) {
                    mma16816(acc[mf][0], a[mf], b0.x, b0.y);
                    mma16816(acc[mf][1], a[mf], b0.z, b0.w);
                    mma16816(acc[mf][2], a[mf], b1v.x, b1v.y);
                    mma16816(acc[mf][3], a[mf], b1v.z, b1v.w);
                }
            }
            if (nh == 0) __syncthreads();        // prior-head fs reads done before hidden overwrite

            // epilogue half: bias + relu + fp16 -> hidden buffer
#pragma unroll
            for (int q2 = 0; q2 < 4; q2++) {
                int n = nh * 128 + ni * 32 + q2 * 8 + ((lane & 3) << 1);
                float bv0 = __ldg(&b1[(h << 8) + n]);
                float bv1 = __ldg(&b1[(h << 8) + n + 1]);
                uint32_t kslab = SM_H + (uint32_t)(n >> 6) * 8192u;
                uint32_t cb = (uint32_t)(n & 63) << 1;
#pragma unroll
                for (int mf = 0; mf < 2; mf++) {
#pragma unroll
                    for (int rr = 0; rr < 2; rr++) {
                        int row = mi * 32 + mf * 16 + (lane >> 2) + rr * 8;
                        float v0 = acc[mf][q2][rr * 2]     + bv0;
                        float v1 = acc[mf][q2][rr * 2 + 1] + bv1;
                        v0 = v0 > 0.f ? v0 : 0.f;
                        v1 = v1 > 0.f ? v1 : 0.f;
                        *(uint32_t*)(smem + kslab + SWZ((uint32_t)((row << 7)) | cb)) = pkf(v0, v1);
                    }
                }
            }
        }
        __syncthreads();

        // ---- GEMM2: C2[64x64] = hidden @ W2[h] (fp16) ----
        float c2[2][2][4];
#pragma unroll
        for (int a = 0; a < 2; a++)
#pragma unroll
            for (int b = 0; b < 2; b++)
#pragma unroll
                for (int c = 0; c < 4; c++) c2[a][b][c] = 0.f;
        {
            const uint4* bp = (const uint4*)g_b2pk + (size_t)h * 2048 + ni * 32 + lane;
#pragma unroll 4
            for (int ks = 0; ks < 16; ks++) {
                uint4 bh = bp[ks * 128];
                const uint32_t kb = ((uint32_t)(ks & 3) << 5) | kboff;
                const uint32_t slab = SM_H + (uint32_t)(ks >> 2) * 8192u;
                uint32_t a[2][4];
#pragma unroll
                for (int mf = 0; mf < 2; mf++)
                    ldsm4(a[mf], sb + slab + SWZ((uint32_t)(((mi * 32 + mf * 16 + rowoff) << 7)) | kb));
#pragma unroll
                for (int mf = 0; mf < 2; mf++) {
                    mma16816(c2[mf][0], a[mf], bh.x, bh.y);
                    mma16816(c2[mf][1], a[mf], bh.z, bh.w);
                }
            }
        }
        __syncthreads();   // all GEMM2 reads of hidden done before fs overwrite

        // ---- epilogue2: bias; store feats (fp16 global, [n][h][64]) + fp32 in SMEM ----
        float* fs = (float*)(smem + SM_H);       // [row][65] fp32
#pragma unroll
        for (int j = 0; j < 2; j++) {
            int n = ni * 16 + j * 8 + ((lane & 3) << 1);
            float bv0 = __ldg(&b2[(h << 6) + n]);
            float bv1 = __ldg(&b2[(h << 6) + n + 1]);
#pragma unroll
            for (int mf = 0; mf < 2; mf++) {
#pragma unroll
                for (int rr = 0; rr < 2; rr++) {
                    int row = mi * 32 + mf * 16 + (lane >> 2) + rr * 8;
                    float v0 = c2[mf][j][rr * 2]     + bv0;
                    float v1 = c2[mf][j][rr * 2 + 1] + bv1;
                    fs[row * 65 + n]     = v0;
                    fs[row * 65 + n + 1] = v1;
                    int gr = m0 + row;
                    if (gr < NN)
                        *(uint32_t*)(g_featsh + ((size_t)gr * NH + h) * OUTD + n) = pkf(v0, v1);
                }
            }
        }
        __syncthreads();

        // ---- attention dots from fp32 feats (warps 0-1, lane = row) ----
        if (wid < 2) {
            int row = wid * 32 + lane;
            int m = m0 + row;
            if (m < NN) {
                const float* fr = fs + row * 65;
                const float* awh = aw + h * (2 * OUTD + 1);
                float s1 = 0.f, s2 = 0.f;
#pragma unroll 8
                for (int c = 0; c < 64; c++) {
                    float v = fr[c];
                    s1 = fmaf(v, __ldg(&awh[c]), s1);
                    s2 = fmaf(v, __ldg(&awh[64 + c]), s2);
                }
                g_ssrc[m * NH + h] = s1 + __ldg(&ab[h]);
                g_sdst[m * NH + h] = s2;
            }
        }
    }
}

// ---------------- edge aggregation: warp per node, all 4 heads ----------------
__global__ __launch_bounds__(256) void k_pool(float* __restrict__ out,
                                              const float* __restrict__ aw) {
    int lane = threadIdx.x & 31;
    int n = blockIdx.x * 8 + (threadIdx.x >> 5);
    if (n >= NN) return;

    int s = g_rowptr[n];
    int e = g_rowptr[n + 1];
    float4 base = *(const float4*)&g_ssrc[n * NH];
    float aw0 = __ldg(&aw[0 * 129 + 128]);
    float aw1 = __ldg(&aw[1 * 129 + 128]);
    float aw2 = __ldg(&aw[2 * 129 + 128]);
    float aw3 = __ldg(&aw[3 * 129 + 128]);
    const __half2* fp = (const __half2*)g_featsh;   // [(n*4+h)*32 + lane]

    float ax0 = 0.f, ay0 = 0.f, ws0 = 0.f;
    float ax1 = 0.f, ay1 = 0.f, ws1 = 0.f;
    float ax2 = 0.f, ay2 = 0.f, ws2 = 0.f;
    float ax3 = 0.f, ay3 = 0.f, ws3 = 0.f;

    for (int i = s; i < e; i++) {
        int d    = g_edst[i];
        float el = g_eelem[i];
        float4 sd = *(const float4*)&g_sdst[(size_t)d * NH];
        const __half2* fd = fp + (size_t)d * (NH * 32) + lane;
        __half2 q0 = fd[0];
        __half2 q1 = fd[32];
        __half2 q2 = fd[64];
        __half2 q3 = fd[96];
        float w0 = __expf(base.x + sd.x + el * aw0);
        float w1 = __expf(base.y + sd.y + el * aw1);
        float w2 = __expf(base.z + sd.z + el * aw2);
        float w3 = __expf(base.w + sd.w + el * aw3);
        float2 f0 = __half22float2(q0), f1 = __half22float2(q1);
        float2 f2 = __half22float2(q2), f3 = __half22float2(q3);
        ax0 = fmaf(w0, f0.x, ax0); ay0 = fmaf(w0, f0.y, ay0); ws0 += w0;
        ax1 = fmaf(w1, f1.x, ax1); ay1 = fmaf(w1, f1.y, ay1); ws1 += w1;
        ax2 = fmaf(w2, f2.x, ax2); ay2 = fmaf(w2, f2.y, ay2); ws2 += w2;
        ax3 = fmaf(w3, f3.x, ax3); ay3 = fmaf(w3, f3.y, ay3); ws3 += w3;
    }

    float* o = out + (size_t)n * (NH * OUTD) + 2 * lane;
    *(float2*)(o)       = make_float2(ax0 / ws0, ay0 / ws0);
    *(float2*)(o + 64)  = make_float2(ax1 / ws1, ay1 / ws1);
    *(float2*)(o + 128) = make_float2(ax2 / ws2, ay2 / ws2);
    *(float2*)(o + 192) = make_float2(ax3 / ws3, ay3 / ws3);
}

// ---------------- launch ----------------
extern "C" void kernel_launch(void* const* d_in, const int* in_sizes, int n_in,
                              void* d_out, int out_size) {
    const float* x    = (const float*)d_in[0];
    const void*  idx  = d_in[1];
    const float* elem = (const float*)d_in[2];
    const float* W1   = (const float*)d_in[3];
    const float* b1   = (const float*)d_in[4];
    const float* W2   = (const float*)d_in[5];
    const float* b2   = (const float*)d_in[6];
    const float* aw   = (const float*)d_in[7];
    const float* ab   = (const float*)d_in[8];
    float* out = (float*)d_out;

    cudaFuncSetAttribute(k_fused, cudaFuncAttributeMaxDynamicSharedMemorySize, SM_TOT);

    k_zero<<<(NN + 255) / 256, 256>>>();
    k_histprep<<<HIST_BLOCKS + (131072 + 32768 + 255) / 256, 256>>>(idx, W1, W2);
    k_scan<<<1, 1024>>>();

    // fused MLP (y==0, head loop) + CSR scatter (y==1)
    dim3 gf(FGRID, 2);
    k_fused<<<gf, 256, SM_TOT>>>(x, b1, b2, aw, ab, idx, elem);

    // aggregation (warp per node, 4 heads)
    k_pool<<<(NN + 7) / 8, 256>>>(out, aw);
}

// round 15
// speedup vs baseline: 3.5267x; 1.1047x over previous
#include <cuda_runtime.h>
#include <cuda_fp16.h>
#include <cstdint>
#include <cstddef>

#define NN 50000
#define NE 800000
#define INDIM 256
#define HID 256
#define OUTD 64
#define NH 4

#define SWZ(o) ((o) ^ (((o) >> 3) & 0x70))

// ---------------- device scratch (static allocation only) ----------------
__device__ int   g_deg[NN];
__device__ int   g_cursor[NN];
__device__ int   g_rowptr[NN + 1];
__device__ int   g_edst[NE];
__device__ float g_eelem[NE];
__device__ __align__(16) __half g_featsh[(size_t)NN * NH * OUTD]; // [n][h][64] fp16
__device__ __align__(16) float g_ssrc[NN * NH];                   // [n][h]
__device__ __align__(16) float g_sdst[NN * NH];                   // [n][h]
// fragment-packed fp16 weights: [h][kstep][nb2][lane][w] uint32 (fp16x2)
__device__ __align__(16) uint32_t g_b1pk[4 * 16 * 16 * 32 * 4];  // 512KB
__device__ __align__(16) uint32_t g_b2pk[4 * 16 * 4 * 32 * 4];   // 128KB

// ---------------- helpers ----------------
__device__ __forceinline__ uint32_t smem_u32(const void* p) {
    uint32_t a;
    asm("{ .reg .u64 t; cvta.to.shared.u64 t, %1; cvt.u32.u64 %0, t; }" : "=r"(a) : "l"(p));
    return a;
}
__device__ __forceinline__ uint32_t pkf(float a, float b) {
    __half2 t = __floats2half2_rn(a, b);
    return reinterpret_cast<uint32_t&>(t);
}
__device__ __forceinline__ void ldsm4(uint32_t* r, uint32_t addr) {
    asm volatile("ldmatrix.sync.aligned.m8n8.x4.shared.b16 {%0,%1,%2,%3}, [%4];"
                 : "=r"(r[0]), "=r"(r[1]), "=r"(r[2]), "=r"(r[3]) : "r"(addr));
}
__device__ __forceinline__ void mma16816(float* c, const uint32_t* a, uint32_t b0, uint32_t b1) {
    asm volatile("mma.sync.aligned.m16n8k16.row.col.f32.f16.f16.f32 "
                 "{%0,%1,%2,%3}, {%4,%5,%6,%7}, {%8,%9}, {%0,%1,%2,%3};"
                 : "+f"(c[0]), "+f"(c[1]), "+f"(c[2]), "+f"(c[3])
                 : "r"(a[0]), "r"(a[1]), "r"(a[2]), "r"(a[3]), "r"(b0), "r"(b1));
}

// ---------------- idx dtype sniff ----------------
__device__ __forceinline__ bool idx_is64(const int* p) {
    return (p[1] | p[3] | p[5] | p[7]) == 0;
}
__device__ __forceinline__ int load_src(const void* idx, int e, bool is64) {
    return is64 ? (int)((const long long*)idx)[e] : ((const int*)idx)[e];
}
__device__ __forceinline__ int load_dst(const void* idx, int e, bool is64) {
    return is64 ? (int)((const long long*)idx)[NE + e] : ((const int*)idx)[NE + e];
}

// ---------------- CSR: zero ----------------
__global__ void k_zero() {
    int i = blockIdx.x * blockDim.x + threadIdx.x;
    if (i < NN) { g_deg[i] = 0; g_cursor[i] = 0; }
}

// ---------------- merged: histogram + weight prep ----------------
#define HIST_BLOCKS 3125
__global__ void k_histprep(const void* __restrict__ idx,
                           const float* __restrict__ W1,
                           const float* __restrict__ W2) {
    int b = blockIdx.x;
    int t = threadIdx.x;
    if (b < HIST_BLOCKS) {
        bool is64 = idx_is64((const int*)idx);
        int e = b * 256 + t;
        if (e < NE) atomicAdd(&g_deg[load_src(idx, e, is64)], 1);
        return;
    }
    int i = (b - HIST_BLOCKS) * 256 + t;
    if (i < 131072) {
        int h = i >> 15;
        int rem = i & 32767;
        int kstep = rem >> 11;
        int rem3 = rem & 2047;
        int nb2 = rem3 >> 7;
        int rem4 = rem3 & 127;
        int lane = rem4 >> 2;
        int w = rem4 & 3;
        int n = nb2 * 16 + ((w >> 1) << 3) + (lane >> 2);
        int k = (kstep << 4) + ((lane & 3) << 1) + ((w & 1) << 3);
        float f0 = W1[((h << 8) + k) * 256 + n];
        float f1 = W1[((h << 8) + k + 1) * 256 + n];
        g_b1pk[i] = pkf(f0, f1);
    } else if (i < 131072 + 32768) {
        int j = i - 131072;
        int h = j >> 13;
        int rem = j & 8191;
        int kstep = rem >> 9;
        int rem3 = rem & 511;
        int nb2 = rem3 >> 7;
        int rem4 = rem3 & 127;
        int lane = rem4 >> 2;
        int w = rem4 & 3;
        int n = nb2 * 16 + ((w >> 1) << 3) + (lane >> 2);
        int k = (kstep << 4) + ((lane & 3) << 1) + ((w & 1) << 3);
        float f0 = W2[((h << 8) + k) * 64 + n];
        float f1 = W2[((h << 8) + k + 1) * 64 + n];
        g_b2pk[j] = pkf(f0, f1);
    }
}

// ---------------- CSR: scan ----------------
__global__ void k_scan() {
    __shared__ int sm[1024];
    const int CH = 49;
    int t = threadIdx.x;
    int base = t * CH, s = 0;
    for (int i = 0; i < CH; i++) { int g = base + i; if (g < NN) s += g_deg[g]; }
    sm[t] = s;
    __syncthreads();
    for (int off = 1; off < 1024; off <<= 1) {
        int v = (t >= off) ? sm[t - off] : 0;
        __syncthreads();
        sm[t] += v;
        __syncthreads();
    }
    int run = sm[t] - s;
    for (int i = 0; i < CH; i++) {
        int g = base + i;
        if (g <= NN) g_rowptr[g] = run;
        if (g < NN)  run += g_deg[g];
    }
}

// ---------------- fused MLP (y==0) + CSR scatter (y==1) ----------------
// SMEM: X fp16 at 0 (32KB: 4 kslabs x 8KB), hidden/fs scratch at 32KB (32KB).
static constexpr uint32_t SM_H   = 32768;
static constexpr uint32_t SM_TOT = 65536;
#define FGRID 782

__global__ __launch_bounds__(256, 2) void k_fused(const float* __restrict__ X,
                                                  const float* __restrict__ b1,
                                                  const float* __restrict__ b2,
                                                  const float* __restrict__ aw,
                                                  const float* __restrict__ ab,
                                                  const void* __restrict__ idx,
                                                  const float* __restrict__ elem) {
    // ----- scatter blocks -----
    if (blockIdx.y == 1) {
        bool is64 = idx_is64((const int*)idx);
        int gt = blockIdx.x * 256 + threadIdx.x;
        for (int e = gt; e < NE; e += FGRID * 256) {
            int s = load_src(idx, e, is64);
            int pos = g_rowptr[s] + atomicAdd(&g_cursor[s], 1);
            g_edst[pos]  = load_dst(idx, e, is64);
            g_eelem[pos] = elem[e];
        }
        return;
    }

    extern __shared__ char smem[];
    const uint32_t sb = smem_u32(smem);
    const int tid  = threadIdx.x;
    const int lane = tid & 31;
    const int wid  = tid >> 5;
    const int m0   = blockIdx.x * 64;

    const int quad = lane >> 3;
    const uint32_t rowoff = ((quad & 1) << 3) | (lane & 7);
    const uint32_t kboff  = (quad >> 1) << 4;

    // ---- stage X (fp16) into SMEM once: 64 rows x 256 cols ----
    {
        const int row = tid >> 2;                // 0..63
        const int kh  = (tid & 3) << 6;          // 0,64,128,192
        const bool rok = (m0 + row) < NN;
        const float* xr = X + (size_t)(m0 + row) * INDIM + kh;
        const uint32_t slab = (uint32_t)(kh >> 6) * 8192u;
#pragma unroll
        for (int c8 = 0; c8 < 8; c8++) {
            float4 v0, v1;
            if (rok) {
                v0 = *(const float4*)(xr + c8 * 8);
                v1 = *(const float4*)(xr + c8 * 8 + 4);
            } else {
                v0 = make_float4(0.f, 0.f, 0.f, 0.f);
                v1 = v0;
            }
            uint32_t off = slab + SWZ((uint32_t)((row << 7) | (c8 << 4)));
            *(uint4*)(smem + off) =
                make_uint4(pkf(v0.x, v0.y), pkf(v0.z, v0.w), pkf(v1.x, v1.y), pkf(v1.z, v1.w));
        }
    }
    __syncthreads();

    const int mi = wid >> 2, ni = wid & 3;       // warp tile: 32 rows x 64 cols

    for (int h = 0; h < NH; h++) {
        // ---- GEMM1: C1[64x256] = X @ W1[h] (fp16, B from L2) ----
        float acc[2][8][4];
#pragma unroll
        for (int a = 0; a < 2; a++)
#pragma unroll
            for (int b = 0; b < 8; b++)
#pragma unroll
                for (int c = 0; c < 4; c++) acc[a][b][c] = 0.f;
        {
            const uint4* bp = (const uint4*)g_b1pk + (size_t)h * 8192 + lane;
#pragma unroll 4
            for (int ks = 0; ks < 16; ks++) {
                uint4 bh[4];
#pragma unroll
                for (int q = 0; q < 4; q++)
                    bh[q] = bp[ks * 512 + (ni * 4 + q) * 32];
                const uint32_t kb = ((uint32_t)(ks & 3) << 5) | kboff;
                const uint32_t slab = (uint32_t)(ks >> 2) * 8192u;
                uint32_t a[2][4];
#pragma unroll
                for (int mf = 0; mf < 2; mf++)
                    ldsm4(a[mf], sb + slab + SWZ((uint32_t)(((mi * 32 + mf * 16 + rowoff) << 7)) | kb));
#pragma unroll
                for (int mf = 0; mf < 2; mf++)
#pragma unroll
                    for (int q = 0; q < 4; q++) {
                        mma16816(acc[mf][q * 2 + 0], a[mf], bh[q].x, bh[q].y);
                        mma16816(acc[mf][q * 2 + 1], a[mf], bh[q].z, bh[q].w);
                    }
            }
        }
        __syncthreads();   // A: prior-head fs reads done before hidden overwrite

        // ---- epilogue1: bias + relu + fp16 -> hidden buffer ----
#pragma unroll
        for (int j = 0; j < 8; j++) {
            int n = ni * 64 + (j >> 1) * 16 + (j & 1) * 8 + ((lane & 3) << 1);
            float bv0 = __ldg(&b1[(h << 8) + n]);
            float bv1 = __ldg(&b1[(h << 8) + n + 1]);
            uint32_t kslab = SM_H + (uint32_t)(n >> 6) * 8192u;
            uint32_t cb = (uint32_t)(n & 63) << 1;
#pragma unroll
            for (int mf = 0; mf < 2; mf++) {
#pragma unroll
                for (int rr = 0; rr < 2; rr++) {
                    int row = mi * 32 + mf * 16 + (lane >> 2) + rr * 8;
                    float v0 = acc[mf][j][rr * 2]     + bv0;
                    float v1 = acc[mf][j][rr * 2 + 1] + bv1;
                    v0 = v0 > 0.f ? v0 : 0.f;
                    v1 = v1 > 0.f ? v1 : 0.f;
                    *(uint32_t*)(smem + kslab + SWZ((uint32_t)((row << 7)) | cb)) = pkf(v0, v1);
                }
            }
        }
        __syncthreads();   // B: hidden visible

        // ---- GEMM2: C2[64x64] = hidden @ W2[h] (fp16, B from L2) ----
        float c2[2][2][4];
#pragma unroll
        for (int a = 0; a < 2; a++)
#pragma unroll
            for (int b = 0; b < 2; b++)
#pragma unroll
                for (int c = 0; c < 4; c++) c2[a][b][c] = 0.f;
        {
            const uint4* bp = (const uint4*)g_b2pk + (size_t)h * 2048 + ni * 32 + lane;
#pragma unroll 4
            for (int ks = 0; ks < 16; ks++) {
                uint4 bh = bp[ks * 128];
                const uint32_t kb = ((uint32_t)(ks & 3) << 5) | kboff;
                const uint32_t slab = SM_H + (uint32_t)(ks >> 2) * 8192u;
                uint32_t a[2][4];
#pragma unroll
                for (int mf = 0; mf < 2; mf++)
                    ldsm4(a[mf], sb + slab + SWZ((uint32_t)(((mi * 32 + mf * 16 + rowoff) << 7)) | kb));
#pragma unroll
                for (int mf = 0; mf < 2; mf++) {
                    mma16816(c2[mf][0], a[mf], bh.x, bh.y);
                    mma16816(c2[mf][1], a[mf], bh.z, bh.w);
                }
            }
        }
        __syncthreads();   // C: GEMM2 reads of hidden done before fs overwrite

        // ---- epilogue2: bias; store feats (fp16 global, [n][h][64]) + fp32 in SMEM ----
        float* fs = (float*)(smem + SM_H);       // [row][65] fp32
#pragma unroll
        for (int j = 0; j < 2; j++) {
            int n = ni * 16 + j * 8 + ((lane & 3) << 1);
            float bv0 = __ldg(&b2[(h << 6) + n]);
            float bv1 = __ldg(&b2[(h << 6) + n + 1]);
#pragma unroll
            for (int mf = 0; mf < 2; mf++) {
#pragma unroll
                for (int rr = 0; rr < 2; rr++) {
                    int row = mi * 32 + mf * 16 + (lane >> 2) + rr * 8;
                    float v0 = c2[mf][j][rr * 2]     + bv0;
                    float v1 = c2[mf][j][rr * 2 + 1] + bv1;
                    fs[row * 65 + n]     = v0;
                    fs[row * 65 + n + 1] = v1;
                    int gr = m0 + row;
                    if (gr < NN)
                        *(uint32_t*)(g_featsh + ((size_t)gr * NH + h) * OUTD + n) = pkf(v0, v1);
                }
            }
        }
        __syncthreads();   // D: fs visible

        // ---- attention dots from fp32 feats: all 8 warps, 8 rows each ----
        {
            const float* awh = aw + h * (2 * OUTD + 1);
            float a0 = __ldg(&awh[2 * lane]);
            float a1 = __ldg(&awh[2 * lane + 1]);
            float a2 = __ldg(&awh[64 + 2 * lane]);
            float a3 = __ldg(&awh[65 + 2 * lane]);
            float bias = __ldg(&ab[h]);
#pragma unroll
            for (int r = 0; r < 8; r++) {
                int row = wid * 8 + r;
                const float* fr = fs + row * 65 + 2 * lane;
                float v0 = fr[0], v1 = fr[1];
                float s1 = v0 * a0 + v1 * a1;
                float s2 = v0 * a2 + v1 * a3;
#pragma unroll
                for (int o = 16; o; o >>= 1) {
                    s1 += __shfl_xor_sync(0xffffffffu, s1, o);
                    s2 += __shfl_xor_sync(0xffffffffu, s2, o);
                }
                int m = m0 + row;
                if (lane == 0 && m < NN) {
                    g_ssrc[m * NH + h] = s1 + bias;
                    g_sdst[m * NH + h] = s2;
                }
            }
        }
        // no barrier: next head's barrier A orders all fs reads before SM_H overwrite
    }
}

// ---------------- edge aggregation: warp per node, all 4 heads ----------------
__global__ __launch_bounds__(256) void k_pool(float* __restrict__ out,
                                              const float* __restrict__ aw) {
    int lane = threadIdx.x & 31;
    int n = blockIdx.x * 8 + (threadIdx.x >> 5);
    if (n >= NN) return;

    int s = g_rowptr[n];
    int e = g_rowptr[n + 1];
    float4 base = *(const float4*)&g_ssrc[n * NH];
    float aw0 = __ldg(&aw[0 * 129 + 128]);
    float aw1 = __ldg(&aw[1 * 129 + 128]);
    float aw2 = __ldg(&aw[2 * 129 + 128]);
    float aw3 = __ldg(&aw[3 * 129 + 128]);
    const __half2* fp = (const __half2*)g_featsh;   // [(n*4+h)*32 + lane]

    float ax0 = 0.f, ay0 = 0.f, ws0 = 0.f;
    float ax1 = 0.f, ay1 = 0.f, ws1 = 0.f;
    float ax2 = 0.f, ay2 = 0.f, ws2 = 0.f;
    float ax3 = 0.f, ay3 = 0.f, ws3 = 0.f;

    for (int i = s; i < e; i++) {
        int d    = g_edst[i];
        float el = g_eelem[i];
        float4 sd = *(const float4*)&g_sdst[(size_t)d * NH];
        const __half2* fd = fp + (size_t)d * (NH * 32) + lane;
        __half2 q0 = fd[0];
        __half2 q1 = fd[32];
        __half2 q2 = fd[64];
        __half2 q3 = fd[96];
        float w0 = __expf(base.x + sd.x + el * aw0);
        float w1 = __expf(base.y + sd.y + el * aw1);
        float w2 = __expf(base.z + sd.z + el * aw2);
        float w3 = __expf(base.w + sd.w + el * aw3);
        float2 f0 = __half22float2(q0), f1 = __half22float2(q1);
        float2 f2 = __half22float2(q2), f3 = __half22float2(q3);
        ax0 = fmaf(w0, f0.x, ax0); ay0 = fmaf(w0, f0.y, ay0); ws0 += w0;
        ax1 = fmaf(w1, f1.x, ax1); ay1 = fmaf(w1, f1.y, ay1); ws1 += w1;
        ax2 = fmaf(w2, f2.x, ax2); ay2 = fmaf(w2, f2.y, ay2); ws2 += w2;
        ax3 = fmaf(w3, f3.x, ax3); ay3 = fmaf(w3, f3.y, ay3); ws3 += w3;
    }

    float* o = out + (size_t)n * (NH * OUTD) + 2 * lane;
    *(float2*)(o)       = make_float2(ax0 / ws0, ay0 / ws0);
    *(float2*)(o + 64)  = make_float2(ax1 / ws1, ay1 / ws1);
    *(float2*)(o + 128) = make_float2(ax2 / ws2, ay2 / ws2);
    *(float2*)(o + 192) = make_float2(ax3 / ws3, ay3 / ws3);
}

// ---------------- launch ----------------
extern "C" void kernel_launch(void* const* d_in, const int* in_sizes, int n_in,
                              void* d_out, int out_size) {
    const float* x    = (const float*)d_in[0];
    const void*  idx  = d_in[1];
    const float* elem = (const float*)d_in[2];
    const float* W1   = (const float*)d_in[3];
    const float* b1   = (const float*)d_in[4];
    const float* W2   = (const float*)d_in[5];
    const float* b2   = (const float*)d_in[6];
    const float* aw   = (const float*)d_in[7];
    const float* ab   = (const float*)d_in[8];
    float* out = (float*)d_out;

    cudaFuncSetAttribute(k_fused, cudaFuncAttributeMaxDynamicSharedMemorySize, SM_TOT);

    k_zero<<<(NN + 255) / 256, 256>>>();
    k_histprep<<<HIST_BLOCKS + (131072 + 32768 + 255) / 256, 256>>>(idx, W1, W2);
    k_scan<<<1, 1024>>>();

    // fused MLP (y==0, head loop) + CSR scatter (y==1)
    dim3 gf(FGRID, 2);
    k_fused<<<gf, 256, SM_TOT>>>(x, b1, b2, aw, ab, idx, elem);

    // aggregation (warp per node, 4 heads)
    k_pool<<<(NN + 7) / 8, 256>>>(out, aw);
}